// round 11
// baseline (speedup 1.0000x reference)
#include <cuda_runtime.h>
#include <cuda_bf16.h>
#include <math.h>
#include <stdint.h>

// ---------------------------------------------------------------------------
// Problem constants
// ---------------------------------------------------------------------------
static constexpr int NN = 50000;    // nodes
static constexpr int NE = 800000;   // edges
static constexpr int F1 = 128;      // in_feats
static constexpr int HF = 256;      // h_feats
static constexpr int CF = 32;       // classes

// ---------------------------------------------------------------------------
// Scratch (device globals -- no allocation allowed)
// ---------------------------------------------------------------------------
__device__ __align__(16) float g_w1 [(size_t)NE * F1];      // layer-1 edge weights (kept for layer 2)
__device__ __align__(16) float g_bufA[(size_t)NE * HF];
__device__ __align__(16) float g_bufB[(size_t)NE * HF];
__device__ __align__(16) float g_h1 [(size_t)NN * HF];
__device__ __align__(16) float g_hN [(size_t)NN * HF];
__device__ __align__(16) float g_cat[(size_t)NN * 2 * HF];
__device__ float g_inv[NN];
__device__ int   g_deg[NN];

// split-bf16 weights, pre-transposed to [N, K] K-major
// offsets (elements): Wr1a=0(16384) Wr1b=16384 We2=32768(32768)
//                     Wr2a=65536(65536) Wr2b=131072 Wl1=196608(65536) Wl2=262144(16384)
static constexpr size_t WT_TOTAL = 278528;
__device__ __align__(16) __nv_bfloat16 g_bwh[WT_TOTAL];
__device__ __align__(16) __nv_bfloat16 g_bwl[WT_TOTAL];

// ---------------------------------------------------------------------------
// helpers
// ---------------------------------------------------------------------------
__device__ __forceinline__ uint32_t smem_u32(const void* p) {
    uint32_t a;
    asm("{ .reg .u64 t; cvta.to.shared.u64 t, %1; cvt.u32.u64 %0, t; }" : "=r"(a) : "l"(p));
    return a;
}

__device__ __forceinline__ void ldm4(uint32_t& r0, uint32_t& r1, uint32_t& r2, uint32_t& r3,
                                     uint32_t addr) {
    asm volatile("ldmatrix.sync.aligned.m8n8.x4.shared.b16 {%0,%1,%2,%3}, [%4];"
                 : "=r"(r0), "=r"(r1), "=r"(r2), "=r"(r3) : "r"(addr));
}

__device__ __forceinline__ void mma16816(float* c, const uint32_t* a, const uint32_t* b) {
    asm volatile("mma.sync.aligned.m16n8k16.row.col.f32.bf16.bf16.f32 "
                 "{%0,%1,%2,%3}, {%4,%5,%6,%7}, {%8,%9}, {%0,%1,%2,%3};"
                 : "+f"(c[0]), "+f"(c[1]), "+f"(c[2]), "+f"(c[3])
                 : "r"(a[0]), "r"(a[1]), "r"(a[2]), "r"(a[3]), "r"(b[0]), "r"(b[1]));
}

// split one fp32 pair into packed bf16 hi + bf16 lo (exact residual then rounded)
__device__ __forceinline__ uint32_t split2(float a, float b, uint32_t& lo) {
    __nv_bfloat16 ha = __float2bfloat16(a), hb = __float2bfloat16(b);
    float ra = a - __bfloat162float(ha);
    float rb = b - __bfloat162float(hb);
    __nv_bfloat16 la = __float2bfloat16(ra), lb = __float2bfloat16(rb);
    lo = (uint32_t)__bfloat16_as_ushort(la) | ((uint32_t)__bfloat16_as_ushort(lb) << 16);
    return (uint32_t)__bfloat16_as_ushort(ha) | ((uint32_t)__bfloat16_as_ushort(hb) << 16);
}

// ---------------------------------------------------------------------------
// Weight pre-transform: W[K,N] fp32 -> Bt_hi/Bt_lo [N,K] bf16
// ---------------------------------------------------------------------------
__global__ void conv_w_kernel(const float* __restrict__ W, int K, int N,
                              __nv_bfloat16* __restrict__ hi, __nv_bfloat16* __restrict__ lo)
{
    const int idx = blockIdx.x * 256 + threadIdx.x;
    if (idx >= K * N) return;
    const int k = idx / N;
    const int n = idx - k * N;
    const float x = W[idx];
    const __nv_bfloat16 h = __float2bfloat16(x);
    const float r = x - __bfloat162float(h);
    hi[(size_t)n * K + k] = h;
    lo[(size_t)n * K + k] = __float2bfloat16(r);
}

// ---------------------------------------------------------------------------
// Fused bf16 split-3 GEMM via mma.sync.m16n8k16 (legacy HMMA, compute_103-safe)
//   A' = A                                   (MSG_IN == false)
//   A'[e,k] = c_e * A[e,k] * h[src[e],k]     (MSG_IN == true)
//   out: store C (SCATTER_OUT=false) or red.add into hN[dst[e],:] (true)
// ---------------------------------------------------------------------------
template<int CTA_N, bool RELU_IN, bool RELU_OUT, bool MSG_IN, bool SCATTER_OUT>
__launch_bounds__(256, 2)
__global__ void gemm_fused(const float* __restrict__ A,
                           const __nv_bfloat16* __restrict__ Bh,
                           const __nv_bfloat16* __restrict__ Bl,
                           const float* __restrict__ bias,
                           float* __restrict__ C,
                           int M, int K, int N,
                           const float* __restrict__ hfeat,
                           const float* __restrict__ invn,
                           const int* __restrict__ src,
                           const int* __restrict__ dst)
{
    extern __shared__ char sm[];
    constexpr int RS    = 144;                 // SMEM row stride bytes (64 bf16 + pad)
    constexpr int S_AHI = 0;
    constexpr int S_ALO = 128 * RS;            // 18432
    constexpr int S_BHI = 2 * 128 * RS;        // 36864
    constexpr int S_BLO = S_BHI + CTA_N * RS;
    constexpr int S_EC  = S_BHI + 2 * CTA_N * RS;   // c_e   [128] float
    constexpr int S_ES  = S_EC + 512;               // src_e [128] int
    constexpr int SPAN  = CTA_N / 2;           // per-warp N span
    constexpr int NI    = SPAN / 8;            // n-tiles per warp

    const int tid    = threadIdx.x;
    const int lane   = tid & 31;
    const int warp   = tid >> 5;
    const int warp_m = warp & 3;
    const int warp_n = warp >> 2;
    const int m0     = blockIdx.x * 128;
    const int n0     = blockIdx.y * CTA_N;

    const uint32_t sb = smem_u32(sm);
    const uint32_t lmo = ((lane & 7) + ((lane >> 3) & 1) * 8) * RS + (lane >> 4) * 16;
    const uint32_t a_base = sb + S_AHI + (uint32_t)(warp_m * 32) * RS + lmo;
    const uint32_t b_base = sb + S_BHI + (uint32_t)(warp_n * SPAN) * RS + lmo;

    // ---- MSG_IN pre-pass: c_e = dot(h[s],h[d]) * inv[s]*inv[d] for 128 edges ----
    if (MSG_IN) {
        for (int r = warp; r < 128; r += 8) {
            const int gm = m0 + r;
            const int s = src[gm];
            const int d = dst[gm];
            const float4* hs4 = reinterpret_cast<const float4*>(hfeat + (size_t)s * K);
            const float4* hd4 = reinterpret_cast<const float4*>(hfeat + (size_t)d * K);
            float dot = 0.f;
            for (int j = 0; j < K / 128; j++) {
                const float4 a = hs4[lane + j * 32];
                const float4 b = hd4[lane + j * 32];
                dot += a.x * b.x + a.y * b.y + a.z * b.z + a.w * b.w;
            }
            #pragma unroll
            for (int o = 16; o > 0; o >>= 1) dot += __shfl_xor_sync(0xFFFFFFFFu, dot, o);
            if (lane == 0) {
                *reinterpret_cast<float*>(sm + S_EC + r * 4) = dot * invn[s] * invn[d];
                *reinterpret_cast<int*>  (sm + S_ES + r * 4) = s;
            }
        }
        __syncthreads();
    }

    float acc[2][NI][4];
    #pragma unroll
    for (int mi = 0; mi < 2; mi++)
        #pragma unroll
        for (int ni = 0; ni < NI; ni++)
            #pragma unroll
            for (int c = 0; c < 4; c++) acc[mi][ni][c] = 0.f;

    const int NC = K >> 6;
    for (int kc = 0; kc < NC; kc++) {
        // ---- A chunk: 128 rows x 64 fp32 -> (optional msg transform) -> split ----
        #pragma unroll
        for (int i = 0; i < 8; i++) {
            const int slot = tid + i * 256;        // 0..2047 (float4 slots)
            const int row  = slot >> 4;
            const int c4   = slot & 15;
            const int gm   = m0 + row;
            float4 v = make_float4(0.f, 0.f, 0.f, 0.f);
            if (gm < M) {
                v = *reinterpret_cast<const float4*>(A + (size_t)gm * K + kc * 64 + c4 * 4);
                if (MSG_IN) {
                    const int   s = *reinterpret_cast<const int*>(sm + S_ES + row * 4);
                    const float c = *reinterpret_cast<const float*>(sm + S_EC + row * 4);
                    const float4 hv = *reinterpret_cast<const float4*>(
                        hfeat + (size_t)s * K + kc * 64 + c4 * 4);
                    v.x = c * v.x * hv.x; v.y = c * v.y * hv.y;
                    v.z = c * v.z * hv.z; v.w = c * v.w * hv.w;
                }
            }
            if (RELU_IN) {
                v.x = fmaxf(v.x, 0.f); v.y = fmaxf(v.y, 0.f);
                v.z = fmaxf(v.z, 0.f); v.w = fmaxf(v.w, 0.f);
            }
            uint32_t l0, l1;
            const uint32_t h0 = split2(v.x, v.y, l0);
            const uint32_t h1 = split2(v.z, v.w, l1);
            const int off = row * RS + c4 * 8;
            *reinterpret_cast<uint2*>(sm + S_AHI + off) = make_uint2(h0, h1);
            *reinterpret_cast<uint2*>(sm + S_ALO + off) = make_uint2(l0, l1);
        }
        // ---- B chunk: CTA_N rows x 64 bf16 (hi & lo) ----
        #pragma unroll
        for (int i = 0; i < CTA_N / 32; i++) {
            const int slot = tid + i * 256;
            const int n    = slot >> 3;
            const int grp  = slot & 7;
            const size_t go = (size_t)(n0 + n) * K + kc * 64 + grp * 8;
            const uint4 vh = *reinterpret_cast<const uint4*>(Bh + go);
            const uint4 vl = *reinterpret_cast<const uint4*>(Bl + go);
            const int off = n * RS + grp * 16;
            *reinterpret_cast<uint4*>(sm + S_BHI + off) = vh;
            *reinterpret_cast<uint4*>(sm + S_BLO + off) = vl;
        }
        __syncthreads();

        // ---- 3 split terms: (Ahi,Bhi), (Ahi,Blo), (Alo,Bhi) ----
        #pragma unroll
        for (int s = 0; s < 3; s++) {
            const uint32_t ab = a_base + ((s == 2) ? (uint32_t)(S_ALO - S_AHI) : 0u);
            const uint32_t bb = b_base + ((s == 1) ? (uint32_t)(CTA_N * RS)    : 0u);
            #pragma unroll
            for (int ks = 0; ks < 4; ks++) {
                uint32_t a[2][4];
                ldm4(a[0][0], a[0][1], a[0][2], a[0][3], ab + ks * 32);
                ldm4(a[1][0], a[1][1], a[1][2], a[1][3], ab + 16 * RS + ks * 32);
                uint32_t b[NI][2];
                #pragma unroll
                for (int p = 0; p < NI / 2; p++) {
                    uint32_t r0, r1, r2, r3;
                    ldm4(r0, r1, r2, r3, bb + (uint32_t)(p * 16) * RS + ks * 32);
                    b[2 * p][0] = r0; b[2 * p + 1][0] = r1;
                    b[2 * p][1] = r2; b[2 * p + 1][1] = r3;
                }
                #pragma unroll
                for (int mi = 0; mi < 2; mi++)
                    #pragma unroll
                    for (int ni = 0; ni < NI; ni++)
                        mma16816(acc[mi][ni], a[mi], b[ni]);
            }
        }
        __syncthreads();
    }

    // ---- epilogue ----
    const int g = lane >> 2;
    const int t = lane & 3;
    #pragma unroll
    for (int mi = 0; mi < 2; mi++) {
        const int gm = m0 + warp_m * 32 + mi * 16 + g;
        int d0 = 0, d1 = 0;
        if (SCATTER_OUT) {
            if (gm < M)     d0 = dst[gm];
            if (gm + 8 < M) d1 = dst[gm + 8];
        }
        #pragma unroll
        for (int ni = 0; ni < NI; ni++) {
            const int gn = n0 + warp_n * SPAN + ni * 8 + t * 2;
            const float2 bb = *reinterpret_cast<const float2*>(bias + gn);
            if (gm < M) {
                float2 o = make_float2(acc[mi][ni][0] + bb.x, acc[mi][ni][1] + bb.y);
                if (RELU_OUT) { o.x = fmaxf(o.x, 0.f); o.y = fmaxf(o.y, 0.f); }
                if (SCATTER_OUT) {
                    asm volatile("red.global.add.v2.f32 [%0], {%1, %2};"
                                 :: "l"(C + (size_t)d0 * N + gn), "f"(o.x), "f"(o.y)
                                 : "memory");
                } else {
                    *reinterpret_cast<float2*>(C + (size_t)gm * N + gn) = o;
                }
            }
            if (gm + 8 < M) {
                float2 o = make_float2(acc[mi][ni][2] + bb.x, acc[mi][ni][3] + bb.y);
                if (RELU_OUT) { o.x = fmaxf(o.x, 0.f); o.y = fmaxf(o.y, 0.f); }
                if (SCATTER_OUT) {
                    asm volatile("red.global.add.v2.f32 [%0], {%1, %2};"
                                 :: "l"(C + (size_t)d1 * N + gn), "f"(o.x), "f"(o.y)
                                 : "memory");
                } else {
                    *reinterpret_cast<float2*>(C + (size_t)(gm + 8) * N + gn) = o;
                }
            }
        }
    }
}

// ---------------------------------------------------------------------------
// w1 = edge_feat @ We1 + be1     (E_IN=2)
// ---------------------------------------------------------------------------
__global__ void w1_kernel(const float* __restrict__ ef, const float* __restrict__ We,
                          const float* __restrict__ be, float* __restrict__ w1)
{
    const int idx = blockIdx.x * 256 + threadIdx.x;
    const int e = idx >> 7;
    const int j = idx & 127;
    const float e0 = ef[2 * e];
    const float e1 = ef[2 * e + 1];
    w1[idx] = fmaf(e1, We[128 + j], fmaf(e0, We[j], be[j]));
}

// ---------------------------------------------------------------------------
// per-node inverse norm
// ---------------------------------------------------------------------------
template<int F>
__global__ void norm_kernel(const float* __restrict__ h, float* __restrict__ invn,
                            int n_nodes)
{
    const int n = blockIdx.x * 8 + (threadIdx.x >> 5);
    if (n >= n_nodes) return;
    const int lane = threadIdx.x & 31;
    const float4* h4 = reinterpret_cast<const float4*>(h + (size_t)n * F);
    float ss = 0.f;
    #pragma unroll
    for (int j = 0; j < F / 128; j++) {
        float4 v = h4[lane + j * 32];
        ss += v.x * v.x + v.y * v.y + v.z * v.z + v.w * v.w;
    }
    #pragma unroll
    for (int o = 16; o > 0; o >>= 1) ss += __shfl_xor_sync(0xFFFFFFFFu, ss, o);
    if (lane == 0) invn[n] = 1.f / fmaxf(sqrtf(ss), 1e-12f);
}

// ---------------------------------------------------------------------------
// degree
// ---------------------------------------------------------------------------
__global__ void deg_kernel(const int* __restrict__ dst, int* __restrict__ deg)
{
    const int e = blockIdx.x * 256 + threadIdx.x;
    if (e < NE) atomicAdd(&deg[dst[e]], 1);
}

// ---------------------------------------------------------------------------
// cat[n, 0:F] = h; cat[n, F:2F] = hN / max(deg, 1)
// ---------------------------------------------------------------------------
template<int F>
__global__ void cat_kernel(const float* __restrict__ h,
                           const float* __restrict__ hN,
                           const int* __restrict__ deg,
                           float* __restrict__ out, int n_nodes)
{
    const int idx = blockIdx.x * 256 + threadIdx.x;
    if (idx >= n_nodes * 2 * F) return;
    const int n = idx / (2 * F);
    const int k = idx - n * 2 * F;
    float v;
    if (k < F) v = h[(size_t)n * F + k];
    else       v = hN[(size_t)n * F + (k - F)] / fmaxf((float)deg[n], 1.f);
    out[idx] = v;
}

// ---------------------------------------------------------------------------
// launch
// ---------------------------------------------------------------------------
extern "C" void kernel_launch(void* const* d_in, const int* in_sizes, int n_in,
                              void* d_out, int out_size)
{
    (void)in_sizes; (void)n_in; (void)out_size;

    const float* nf   = (const float*)d_in[0];
    const float* ef   = (const float*)d_in[1];
    const int*   src  = (const int*)  d_in[2];
    const int*   dst  = (const int*)  d_in[3];
    const float* We1  = (const float*)d_in[4];
    const float* be1  = (const float*)d_in[5];
    const float* Wr1a = (const float*)d_in[6];
    const float* br1a = (const float*)d_in[7];
    const float* Wr1b = (const float*)d_in[8];
    const float* br1b = (const float*)d_in[9];
    const float* Wl1  = (const float*)d_in[10];
    const float* bl1  = (const float*)d_in[11];
    const float* We2  = (const float*)d_in[12];
    const float* be2  = (const float*)d_in[13];
    const float* Wr2a = (const float*)d_in[14];
    const float* br2a = (const float*)d_in[15];
    const float* Wr2b = (const float*)d_in[16];
    const float* br2b = (const float*)d_in[17];
    const float* Wl2  = (const float*)d_in[18];
    const float* bl2  = (const float*)d_in[19];
    float* out = (float*)d_out;

    float *p_w1, *p_A, *p_B, *p_h1, *p_hN, *p_cat, *p_inv;
    int*   p_deg;
    __nv_bfloat16 *p_bwh, *p_bwl;
    cudaGetSymbolAddress((void**)&p_w1,  g_w1);
    cudaGetSymbolAddress((void**)&p_A,   g_bufA);
    cudaGetSymbolAddress((void**)&p_B,   g_bufB);
    cudaGetSymbolAddress((void**)&p_h1,  g_h1);
    cudaGetSymbolAddress((void**)&p_hN,  g_hN);
    cudaGetSymbolAddress((void**)&p_cat, g_cat);
    cudaGetSymbolAddress((void**)&p_inv, g_inv);
    cudaGetSymbolAddress((void**)&p_deg, g_deg);
    cudaGetSymbolAddress((void**)&p_bwh, g_bwh);
    cudaGetSymbolAddress((void**)&p_bwl, g_bwl);

    // dynamic SMEM: 2*128*144 (A) + 2*CTA_N*144 (B) + 1KB (msg pre-pass)
    constexpr int SMN128 = 36864 + 128 * 288 + 1024;   // 74752
    constexpr int SMN32  = 36864 + 32  * 288 + 1024;   // 47104
    cudaFuncSetAttribute(gemm_fused<128, false, true,  false, false>, cudaFuncAttributeMaxDynamicSharedMemorySize, SMN128);
    cudaFuncSetAttribute(gemm_fused<128, true,  false, false, false>, cudaFuncAttributeMaxDynamicSharedMemorySize, SMN128);
    cudaFuncSetAttribute(gemm_fused<128, false, true,  true,  false>, cudaFuncAttributeMaxDynamicSharedMemorySize, SMN128);
    cudaFuncSetAttribute(gemm_fused<128, false, true,  false, true >, cudaFuncAttributeMaxDynamicSharedMemorySize, SMN128);
    cudaFuncSetAttribute(gemm_fused<32,  false, false, false, false>, cudaFuncAttributeMaxDynamicSharedMemorySize, SMN32);

    const int EG = NE / 128;              // 6250 edge M-tiles
    const int VG = (NN + 127) / 128;      // 391 node M-tiles

    // ---- zero accumulators FIRST, then independent prep ----
    cudaMemsetAsync(p_deg, 0, NN * sizeof(int));
    cudaMemsetAsync(p_hN, 0, (size_t)NN * F1 * sizeof(float));

    conv_w_kernel<<<(128 * 128 + 255) / 256, 256>>>(Wr1a, 128, 128, p_bwh + 0,     p_bwl + 0);
    w1_kernel<<<(NE * F1) / 256, 256>>>(ef, We1, be1, p_w1);
    norm_kernel<F1><<<(NN + 7) / 8, 256>>>(nf, p_inv, NN);
    conv_w_kernel<<<(128 * 128 + 255) / 256, 256>>>(Wr1b, 128, 128, p_bwh + 16384, p_bwl + 16384);
    deg_kernel<<<(NE + 255) / 256, 256>>>(dst, p_deg);

    // ======================= layer 1 =======================
    // fused msg + GEMM(Wr1a): r1 = relu( (c*w1*nf[src]) @ Wr1a + br1a )
    gemm_fused<128, false, true, true, false><<<dim3(EG, 1), 256, SMN128>>>(
        p_w1, p_bwh + 0, p_bwl + 0, br1a, p_B, NE, 128, 128, nf, p_inv, src, dst);

    // fused GEMM(Wr1b) + scatter: hN[dst] += relu( r1 @ Wr1b + br1b )
    gemm_fused<128, false, true, false, true><<<dim3(EG, 1), 256, SMN128>>>(
        p_B, p_bwh + 16384, p_bwl + 16384, br1b, p_hN, NE, 128, 128,
        nullptr, nullptr, nullptr, dst);

    // remaining weight pre-splits (independent of layer-1 chain)
    conv_w_kernel<<<(128 * 256 + 255) / 256, 256>>>(We2,  128, 256, p_bwh + 32768,  p_bwl + 32768);
    conv_w_kernel<<<(256 * 256 + 255) / 256, 256>>>(Wr2a, 256, 256, p_bwh + 65536,  p_bwl + 65536);
    conv_w_kernel<<<(256 * 256 + 255) / 256, 256>>>(Wr2b, 256, 256, p_bwh + 131072, p_bwl + 131072);
    conv_w_kernel<<<(256 * 256 + 255) / 256, 256>>>(Wl1,  256, 256, p_bwh + 196608, p_bwl + 196608);
    conv_w_kernel<<<(512 * 32  + 255) / 256, 256>>>(Wl2,  512, 32,  p_bwh + 262144, p_bwl + 262144);

    cat_kernel<F1><<<(NN * 2 * F1 + 255) / 256, 256>>>(nf, p_hN, p_deg, p_cat, NN);

    gemm_fused<128, false, true, false, false><<<dim3(VG, 2), 256, SMN128>>>(
        p_cat, p_bwh + 196608, p_bwl + 196608, bl1, p_h1, NN, 256, 256,
        nullptr, nullptr, nullptr, nullptr);

    // ======================= layer 2 =======================
    // w2 = relu(w1) @ We2 + be2   (relu fused into A split)
    gemm_fused<128, true, false, false, false><<<dim3(EG, 2), 256, SMN128>>>(
        p_w1, p_bwh + 32768, p_bwl + 32768, be2, p_A, NE, 128, 256,
        nullptr, nullptr, nullptr, nullptr);

    norm_kernel<HF><<<(NN + 7) / 8, 256>>>(p_h1, p_inv, NN);
    cudaMemsetAsync(p_hN, 0, (size_t)NN * HF * sizeof(float));

    // fused msg + GEMM(Wr2a): r1 = relu( (c*w2*h1[src]) @ Wr2a + br2a )
    gemm_fused<128, false, true, true, false><<<dim3(EG, 2), 256, SMN128>>>(
        p_A, p_bwh + 65536, p_bwl + 65536, br2a, p_B, NE, 256, 256,
        p_h1, p_inv, src, dst);

    // fused GEMM(Wr2b) + scatter: hN[dst] += relu( r1 @ Wr2b + br2b )
    gemm_fused<128, false, true, false, true><<<dim3(EG, 2), 256, SMN128>>>(
        p_B, p_bwh + 131072, p_bwl + 131072, br2b, p_hN, NE, 256, 256,
        nullptr, nullptr, nullptr, dst);

    cat_kernel<HF><<<(NN * 2 * HF + 255) / 256, 256>>>(p_h1, p_hN, p_deg, p_cat, NN);

    gemm_fused<32, false, false, false, false><<<dim3(VG, 1), 256, SMN32>>>(
        p_cat, p_bwh + 262144, p_bwl + 262144, bl2, out, NN, 512, 32,
        nullptr, nullptr, nullptr, nullptr);
}

// round 12
// speedup vs baseline: 1.1525x; 1.1525x over previous
#include <cuda_runtime.h>
#include <cuda_bf16.h>
#include <math.h>
#include <stdint.h>

// ---------------------------------------------------------------------------
// Problem constants
// ---------------------------------------------------------------------------
static constexpr int NN = 50000;    // nodes
static constexpr int NE = 800000;   // edges
static constexpr int F1 = 128;      // in_feats
static constexpr int HF = 256;      // h_feats
static constexpr int CF = 32;       // classes

// ---------------------------------------------------------------------------
// Scratch (device globals -- no allocation allowed)
// ---------------------------------------------------------------------------
__device__ __align__(16) float g_w1 [(size_t)NE * F1];      // layer-1 edge weights (kept for layer 2)
__device__ __align__(16) float g_bufA[(size_t)NE * HF];
__device__ __align__(16) float g_bufB[(size_t)NE * HF];
__device__ __align__(16) float g_h1 [(size_t)NN * HF];
__device__ __align__(16) float g_hN [(size_t)NN * HF];
__device__ __align__(16) float g_cat[(size_t)NN * 2 * HF];
__device__ float g_inv[NN];
__device__ int   g_deg[NN];

// split-bf16 weights, pre-transposed to [N, K] K-major
// offsets (elements): Wr1a=0(16384) Wr1b=16384 We2=32768(32768)
//                     Wr2a=65536(65536) Wr2b=131072 Wl1=196608(65536) Wl2=262144(16384)
static constexpr size_t WT_TOTAL = 278528;
__device__ __align__(16) __nv_bfloat16 g_bwh[WT_TOTAL];
__device__ __align__(16) __nv_bfloat16 g_bwl[WT_TOTAL];

// ---------------------------------------------------------------------------
// helpers
// ---------------------------------------------------------------------------
__device__ __forceinline__ uint32_t smem_u32(const void* p) {
    uint32_t a;
    asm("{ .reg .u64 t; cvta.to.shared.u64 t, %1; cvt.u32.u64 %0, t; }" : "=r"(a) : "l"(p));
    return a;
}

__device__ __forceinline__ void ldm4(uint32_t& r0, uint32_t& r1, uint32_t& r2, uint32_t& r3,
                                     uint32_t addr) {
    asm volatile("ldmatrix.sync.aligned.m8n8.x4.shared.b16 {%0,%1,%2,%3}, [%4];"
                 : "=r"(r0), "=r"(r1), "=r"(r2), "=r"(r3) : "r"(addr));
}

__device__ __forceinline__ void mma16816(float* c, const uint32_t* a, const uint32_t* b) {
    asm volatile("mma.sync.aligned.m16n8k16.row.col.f32.bf16.bf16.f32 "
                 "{%0,%1,%2,%3}, {%4,%5,%6,%7}, {%8,%9}, {%0,%1,%2,%3};"
                 : "+f"(c[0]), "+f"(c[1]), "+f"(c[2]), "+f"(c[3])
                 : "r"(a[0]), "r"(a[1]), "r"(a[2]), "r"(a[3]), "r"(b[0]), "r"(b[1]));
}

// split one fp32 pair into packed bf16 hi + bf16 lo (exact residual then rounded)
__device__ __forceinline__ uint32_t split2(float a, float b, uint32_t& lo) {
    __nv_bfloat16 ha = __float2bfloat16(a), hb = __float2bfloat16(b);
    float ra = a - __bfloat162float(ha);
    float rb = b - __bfloat162float(hb);
    __nv_bfloat16 la = __float2bfloat16(ra), lb = __float2bfloat16(rb);
    lo = (uint32_t)__bfloat16_as_ushort(la) | ((uint32_t)__bfloat16_as_ushort(lb) << 16);
    return (uint32_t)__bfloat16_as_ushort(ha) | ((uint32_t)__bfloat16_as_ushort(hb) << 16);
}

// ---------------------------------------------------------------------------
// Weight pre-transform: W[K,N] fp32 -> Bt_hi/Bt_lo [N,K] bf16
// ---------------------------------------------------------------------------
__global__ void conv_w_kernel(const float* __restrict__ W, int K, int N,
                              __nv_bfloat16* __restrict__ hi, __nv_bfloat16* __restrict__ lo)
{
    const int idx = blockIdx.x * 256 + threadIdx.x;
    if (idx >= K * N) return;
    const int k = idx / N;
    const int n = idx - k * N;
    const float x = W[idx];
    const __nv_bfloat16 h = __float2bfloat16(x);
    const float r = x - __bfloat162float(h);
    hi[(size_t)n * K + k] = h;
    lo[(size_t)n * K + k] = __float2bfloat16(r);
}

// ---------------------------------------------------------------------------
// bf16 split-3 GEMM via mma.sync.m16n8k16, with cp.async A-chunk staging:
// while chunk kc's MMAs run, chunk kc+1's raw fp32 A rows stream into a
// 32KB SMEM staging buffer (cp.async.cg).  The convert/split step reads
// the stage from SMEM, so no DRAM latency sits on the critical path.
// C[M,N] = act_out( act_in(A[M,K]) @ B[K,N] + bias );  B pre-split [N,K].
// CTA tile 128(M) x CTA_N; 8 warps 4(M)x2(N); SMEM rows padded to 144B.
// ---------------------------------------------------------------------------
template<int CTA_N, bool RELU_IN, bool RELU_OUT>
__launch_bounds__(256, 2)
__global__ void gemm_mma(const float* __restrict__ A,
                         const __nv_bfloat16* __restrict__ Bh,
                         const __nv_bfloat16* __restrict__ Bl,
                         const float* __restrict__ bias,
                         float* __restrict__ C,
                         int M, int K, int N)
{
    extern __shared__ char sm[];
    constexpr int RS    = 144;                 // SMEM row stride bytes (64 bf16 + pad)
    constexpr int S_AHI = 0;
    constexpr int S_ALO = 128 * RS;            // 18432
    constexpr int S_BHI = 2 * 128 * RS;        // 36864
    constexpr int S_BLO = S_BHI + CTA_N * RS;
    constexpr int S_STG = S_BHI + 2 * CTA_N * RS;  // fp32 A staging: 128x64x4 = 32768
    constexpr int SPAN  = CTA_N / 2;           // per-warp N span
    constexpr int NI    = SPAN / 8;            // n-tiles per warp

    const int tid    = threadIdx.x;
    const int lane   = tid & 31;
    const int warp   = tid >> 5;
    const int warp_m = warp & 3;
    const int warp_n = warp >> 2;
    const int m0     = blockIdx.x * 128;
    const int n0     = blockIdx.y * CTA_N;

    const uint32_t sb = smem_u32(sm);
    // ldmatrix lane offset: rows (lane&7)+8*((lane>>3)&1), col-group (lane>>4)*8 elems
    const uint32_t lmo = ((lane & 7) + ((lane >> 3) & 1) * 8) * RS + (lane >> 4) * 16;
    const uint32_t a_base = sb + S_AHI + (uint32_t)(warp_m * 32) * RS + lmo;
    const uint32_t b_base = sb + S_BHI + (uint32_t)(warp_n * SPAN) * RS + lmo;

    float acc[2][NI][4];
    #pragma unroll
    for (int mi = 0; mi < 2; mi++)
        #pragma unroll
        for (int ni = 0; ni < NI; ni++)
            #pragma unroll
            for (int c = 0; c < 4; c++) acc[mi][ni][c] = 0.f;

    // cp.async of one A chunk (128 rows x 64 fp32) into the staging buffer.
    // OOB rows (gm >= M) use src-size 0 -> zero-fill.
    auto cp_stage = [&](int kc) {
        #pragma unroll
        for (int i = 0; i < 8; i++) {
            const int slot = tid + i * 256;        // 0..2047 (16B slots)
            const int row  = slot >> 4;
            const int c4   = slot & 15;
            const int gm   = m0 + row;
            const bool ok  = (gm < M);
            const float* gp = A + (size_t)(ok ? gm : m0) * K + kc * 64 + c4 * 4;
            const uint32_t dp = sb + S_STG + (uint32_t)slot * 16;
            const int ssz = ok ? 16 : 0;
            asm volatile("cp.async.cg.shared.global [%0], [%1], 16, %2;"
                         :: "r"(dp), "l"(gp), "r"(ssz) : "memory");
        }
        asm volatile("cp.async.commit_group;" ::: "memory");
    };

    const int NC = K >> 6;
    cp_stage(0);
    asm volatile("cp.async.wait_group 0;" ::: "memory");
    __syncthreads();

    for (int kc = 0; kc < NC; kc++) {
        // ---- convert staged fp32 chunk -> split bf16 hi/lo in SMEM ----
        #pragma unroll
        for (int i = 0; i < 8; i++) {
            const int slot = tid + i * 256;
            const int row  = slot >> 4;
            const int c4   = slot & 15;
            float4 v = *reinterpret_cast<const float4*>(sm + S_STG + (size_t)slot * 16);
            if (RELU_IN) {
                v.x = fmaxf(v.x, 0.f); v.y = fmaxf(v.y, 0.f);
                v.z = fmaxf(v.z, 0.f); v.w = fmaxf(v.w, 0.f);
            }
            uint32_t l0, l1;
            const uint32_t h0 = split2(v.x, v.y, l0);
            const uint32_t h1 = split2(v.z, v.w, l1);
            const int off = row * RS + c4 * 8;
            *reinterpret_cast<uint2*>(sm + S_AHI + off) = make_uint2(h0, h1);
            *reinterpret_cast<uint2*>(sm + S_ALO + off) = make_uint2(l0, l1);
        }
        // ---- B chunk: CTA_N rows x 64 bf16 (hi & lo), L2-hot weights ----
        #pragma unroll
        for (int i = 0; i < CTA_N / 32; i++) {
            const int slot = tid + i * 256;        // uint4 slots
            const int n    = slot >> 3;
            const int grp  = slot & 7;
            const size_t go = (size_t)(n0 + n) * K + kc * 64 + grp * 8;
            const uint4 vh = *reinterpret_cast<const uint4*>(Bh + go);
            const uint4 vl = *reinterpret_cast<const uint4*>(Bl + go);
            const int off = n * RS + grp * 16;
            *reinterpret_cast<uint4*>(sm + S_BHI + off) = vh;
            *reinterpret_cast<uint4*>(sm + S_BLO + off) = vl;
        }
        __syncthreads();   // A/B tiles ready; all reads of stage complete

        // ---- prefetch next A chunk into stage; overlaps the MMA block ----
        if (kc + 1 < NC) cp_stage(kc + 1);

        // ---- 3 split terms: (Ahi,Bhi), (Ahi,Blo), (Alo,Bhi) ----
        #pragma unroll
        for (int s = 0; s < 3; s++) {
            const uint32_t ab = a_base + ((s == 2) ? (uint32_t)(S_ALO - S_AHI) : 0u);
            const uint32_t bb = b_base + ((s == 1) ? (uint32_t)(CTA_N * RS)    : 0u);
            #pragma unroll
            for (int ks = 0; ks < 4; ks++) {
                uint32_t a[2][4];
                ldm4(a[0][0], a[0][1], a[0][2], a[0][3], ab + ks * 32);
                ldm4(a[1][0], a[1][1], a[1][2], a[1][3], ab + 16 * RS + ks * 32);
                uint32_t b[NI][2];
                #pragma unroll
                for (int p = 0; p < NI / 2; p++) {
                    uint32_t r0, r1, r2, r3;
                    ldm4(r0, r1, r2, r3, bb + (uint32_t)(p * 16) * RS + ks * 32);
                    b[2 * p][0] = r0; b[2 * p + 1][0] = r1;
                    b[2 * p][1] = r2; b[2 * p + 1][1] = r3;
                }
                #pragma unroll
                for (int mi = 0; mi < 2; mi++)
                    #pragma unroll
                    for (int ni = 0; ni < NI; ni++)
                        mma16816(acc[mi][ni], a[mi], b[ni]);
            }
        }
        asm volatile("cp.async.wait_group 0;" ::: "memory");
        __syncthreads();   // stage filled; A/B SMEM reusable
    }

    // ---- epilogue: bias (+relu), float2 stores ----
    const int g = lane >> 2;
    const int t = lane & 3;
    #pragma unroll
    for (int mi = 0; mi < 2; mi++) {
        const int gm = m0 + warp_m * 32 + mi * 16 + g;
        #pragma unroll
        for (int ni = 0; ni < NI; ni++) {
            const int gn = n0 + warp_n * SPAN + ni * 8 + t * 2;
            const float2 bb = *reinterpret_cast<const float2*>(bias + gn);
            if (gm < M) {
                float2 o = make_float2(acc[mi][ni][0] + bb.x, acc[mi][ni][1] + bb.y);
                if (RELU_OUT) { o.x = fmaxf(o.x, 0.f); o.y = fmaxf(o.y, 0.f); }
                *reinterpret_cast<float2*>(C + (size_t)gm * N + gn) = o;
            }
            if (gm + 8 < M) {
                float2 o = make_float2(acc[mi][ni][2] + bb.x, acc[mi][ni][3] + bb.y);
                if (RELU_OUT) { o.x = fmaxf(o.x, 0.f); o.y = fmaxf(o.y, 0.f); }
                *reinterpret_cast<float2*>(C + (size_t)(gm + 8) * N + gn) = o;
            }
        }
    }
}

// ---------------------------------------------------------------------------
// w1 = edge_feat @ We1 + be1     (E_IN=2)
// ---------------------------------------------------------------------------
__global__ void w1_kernel(const float* __restrict__ ef, const float* __restrict__ We,
                          const float* __restrict__ be, float* __restrict__ w1)
{
    const int idx = blockIdx.x * 256 + threadIdx.x;
    const int e = idx >> 7;
    const int j = idx & 127;
    const float e0 = ef[2 * e];
    const float e1 = ef[2 * e + 1];
    w1[idx] = fmaf(e1, We[128 + j], fmaf(e0, We[j], be[j]));
}

// ---------------------------------------------------------------------------
// per-node inverse norm
// ---------------------------------------------------------------------------
template<int F>
__global__ void norm_kernel(const float* __restrict__ h, float* __restrict__ invn,
                            int n_nodes)
{
    const int n = blockIdx.x * 8 + (threadIdx.x >> 5);
    if (n >= n_nodes) return;
    const int lane = threadIdx.x & 31;
    const float4* h4 = reinterpret_cast<const float4*>(h + (size_t)n * F);
    float ss = 0.f;
    #pragma unroll
    for (int j = 0; j < F / 128; j++) {
        float4 v = h4[lane + j * 32];
        ss += v.x * v.x + v.y * v.y + v.z * v.z + v.w * v.w;
    }
    #pragma unroll
    for (int o = 16; o > 0; o >>= 1) ss += __shfl_xor_sync(0xFFFFFFFFu, ss, o);
    if (lane == 0) invn[n] = 1.f / fmaxf(sqrtf(ss), 1e-12f);
}

// ---------------------------------------------------------------------------
// per-edge message: m[e,:] = cos_e * w[e,:] * h[src[e],:]
// ---------------------------------------------------------------------------
template<int F>
__global__ void msg_kernel(const float* __restrict__ h,
                           const float* w, float* m,
                           const float* __restrict__ invn,
                           const int* __restrict__ src,
                           const int* __restrict__ dst)
{
    const int e    = blockIdx.x * 8 + (threadIdx.x >> 5);
    const int lane = threadIdx.x & 31;
    const int s = src[e];
    const int d = dst[e];
    const float4* hs4 = reinterpret_cast<const float4*>(h + (size_t)s * F);
    const float4* hd4 = reinterpret_cast<const float4*>(h + (size_t)d * F);
    float4 a[F / 128];
    float dot = 0.f;
    #pragma unroll
    for (int j = 0; j < F / 128; j++) {
        a[j] = hs4[lane + j * 32];
        float4 b = hd4[lane + j * 32];
        dot += a[j].x * b.x + a[j].y * b.y + a[j].z * b.z + a[j].w * b.w;
    }
    #pragma unroll
    for (int o = 16; o > 0; o >>= 1) dot += __shfl_xor_sync(0xFFFFFFFFu, dot, o);
    const float c = dot * invn[s] * invn[d];
    const float4* w4 = reinterpret_cast<const float4*>(w + (size_t)e * F);
    float4*       m4 = reinterpret_cast<float4*>(m + (size_t)e * F);
    #pragma unroll
    for (int j = 0; j < F / 128; j++) {
        float4 wv = w4[lane + j * 32];
        float4 o;
        o.x = c * wv.x * a[j].x;
        o.y = c * wv.y * a[j].y;
        o.z = c * wv.z * a[j].z;
        o.w = c * wv.w * a[j].w;
        m4[lane + j * 32] = o;
    }
}

// ---------------------------------------------------------------------------
// degree + vectorized scatter-sum (red.global.add.v4.f32, sm_90+)
// ---------------------------------------------------------------------------
__global__ void deg_kernel(const int* __restrict__ dst, int* __restrict__ deg)
{
    const int e = blockIdx.x * 256 + threadIdx.x;
    if (e < NE) atomicAdd(&deg[dst[e]], 1);
}

template<int F>
__global__ void scatter_kernel(const float* __restrict__ r,
                               const int* __restrict__ dst,
                               float* hN)
{
    const int e    = blockIdx.x * 8 + (threadIdx.x >> 5);
    const int lane = threadIdx.x & 31;
    const int d = dst[e];
    const float4* rr = reinterpret_cast<const float4*>(r + (size_t)e * F);
    float* out = hN + (size_t)d * F;
    #pragma unroll
    for (int j = 0; j < F / 128; j++) {
        const float4 v = rr[lane + j * 32];
        asm volatile("red.global.add.v4.f32 [%0], {%1, %2, %3, %4};"
                     :: "l"(out + lane * 4 + j * 128),
                        "f"(v.x), "f"(v.y), "f"(v.z), "f"(v.w) : "memory");
    }
}

// ---------------------------------------------------------------------------
// cat[n, 0:F] = h; cat[n, F:2F] = hN / max(deg, 1)
// ---------------------------------------------------------------------------
template<int F>
__global__ void cat_kernel(const float* __restrict__ h,
                           const float* __restrict__ hN,
                           const int* __restrict__ deg,
                           float* __restrict__ out, int n_nodes)
{
    const int idx = blockIdx.x * 256 + threadIdx.x;
    if (idx >= n_nodes * 2 * F) return;
    const int n = idx / (2 * F);
    const int k = idx - n * 2 * F;
    float v;
    if (k < F) v = h[(size_t)n * F + k];
    else       v = hN[(size_t)n * F + (k - F)] / fmaxf((float)deg[n], 1.f);
    out[idx] = v;
}

// ---------------------------------------------------------------------------
// launch  (launch #6 is the first big edge GEMM for ncu -s 5 -c 1)
// ---------------------------------------------------------------------------
extern "C" void kernel_launch(void* const* d_in, const int* in_sizes, int n_in,
                              void* d_out, int out_size)
{
    (void)in_sizes; (void)n_in; (void)out_size;

    const float* nf   = (const float*)d_in[0];
    const float* ef   = (const float*)d_in[1];
    const int*   src  = (const int*)  d_in[2];
    const int*   dst  = (const int*)  d_in[3];
    const float* We1  = (const float*)d_in[4];
    const float* be1  = (const float*)d_in[5];
    const float* Wr1a = (const float*)d_in[6];
    const float* br1a = (const float*)d_in[7];
    const float* Wr1b = (const float*)d_in[8];
    const float* br1b = (const float*)d_in[9];
    const float* Wl1  = (const float*)d_in[10];
    const float* bl1  = (const float*)d_in[11];
    const float* We2  = (const float*)d_in[12];
    const float* be2  = (const float*)d_in[13];
    const float* Wr2a = (const float*)d_in[14];
    const float* br2a = (const float*)d_in[15];
    const float* Wr2b = (const float*)d_in[16];
    const float* br2b = (const float*)d_in[17];
    const float* Wl2  = (const float*)d_in[18];
    const float* bl2  = (const float*)d_in[19];
    float* out = (float*)d_out;

    float *p_w1, *p_A, *p_B, *p_h1, *p_hN, *p_cat, *p_inv;
    int*   p_deg;
    __nv_bfloat16 *p_bwh, *p_bwl;
    cudaGetSymbolAddress((void**)&p_w1,  g_w1);
    cudaGetSymbolAddress((void**)&p_A,   g_bufA);
    cudaGetSymbolAddress((void**)&p_B,   g_bufB);
    cudaGetSymbolAddress((void**)&p_h1,  g_h1);
    cudaGetSymbolAddress((void**)&p_hN,  g_hN);
    cudaGetSymbolAddress((void**)&p_cat, g_cat);
    cudaGetSymbolAddress((void**)&p_inv, g_inv);
    cudaGetSymbolAddress((void**)&p_deg, g_deg);
    cudaGetSymbolAddress((void**)&p_bwh, g_bwh);
    cudaGetSymbolAddress((void**)&p_bwl, g_bwl);

    // dynamic SMEM: 2*128*144 (A) + 2*CTA_N*144 (B) + 32768 (fp32 A stage)
    constexpr int SMN128 = 36864 + 128 * 288 + 32768;   // 106496 -> 2 CTAs/SM
    constexpr int SMN32  = 36864 + 32  * 288 + 32768;   // 78848
    cudaFuncSetAttribute(gemm_mma<128, false, true >, cudaFuncAttributeMaxDynamicSharedMemorySize, SMN128);
    cudaFuncSetAttribute(gemm_mma<128, true,  false>, cudaFuncAttributeMaxDynamicSharedMemorySize, SMN128);
    cudaFuncSetAttribute(gemm_mma<32,  false, false>, cudaFuncAttributeMaxDynamicSharedMemorySize, SMN32);

    const int EG = NE / 128;              // 6250 edge M-tiles
    const int VG = (NN + 127) / 128;      // 391 node M-tiles

    // ======================= layer 1 (front-loaded for profiling) ==========
    // launches 1..5
    conv_w_kernel<<<(128 * 128 + 255) / 256, 256>>>(Wr1a, 128, 128, p_bwh + 0,     p_bwl + 0);
    w1_kernel<<<(NE * F1) / 256, 256>>>(ef, We1, be1, p_w1);
    norm_kernel<F1><<<(NN + 7) / 8, 256>>>(nf, p_inv, NN);
    msg_kernel<F1><<<NE / 8, 256>>>(nf, p_w1, p_A, p_inv, src, dst);
    conv_w_kernel<<<(128 * 128 + 255) / 256, 256>>>(Wr1b, 128, 128, p_bwh + 16384, p_bwl + 16384);

    // launch 6: ncu (-s 5 -c 1) captures THIS -- first big edge GEMM
    gemm_mma<128, false, true><<<dim3(EG, 1), 256, SMN128>>>(p_A, p_bwh + 0,     p_bwl + 0,     br1a, p_B, NE, 128, 128);
    gemm_mma<128, false, true><<<dim3(EG, 1), 256, SMN128>>>(p_B, p_bwh + 16384, p_bwl + 16384, br1b, p_A, NE, 128, 128);

    // remaining weight pre-splits + degree (independent of GEMMs above)
    conv_w_kernel<<<(128 * 256 + 255) / 256, 256>>>(We2,  128, 256, p_bwh + 32768,  p_bwl + 32768);
    conv_w_kernel<<<(256 * 256 + 255) / 256, 256>>>(Wr2a, 256, 256, p_bwh + 65536,  p_bwl + 65536);
    conv_w_kernel<<<(256 * 256 + 255) / 256, 256>>>(Wr2b, 256, 256, p_bwh + 131072, p_bwl + 131072);
    conv_w_kernel<<<(256 * 256 + 255) / 256, 256>>>(Wl1,  256, 256, p_bwh + 196608, p_bwl + 196608);
    conv_w_kernel<<<(512 * 32  + 255) / 256, 256>>>(Wl2,  512, 32,  p_bwh + 262144, p_bwl + 262144);
    cudaMemsetAsync(p_deg, 0, NN * sizeof(int));
    deg_kernel<<<(NE + 255) / 256, 256>>>(dst, p_deg);

    cudaMemsetAsync(p_hN, 0, (size_t)NN * F1 * sizeof(float));
    scatter_kernel<F1><<<NE / 8, 256>>>(p_A, dst, p_hN);
    cat_kernel<F1><<<(NN * 2 * F1 + 255) / 256, 256>>>(nf, p_hN, p_deg, p_cat, NN);

    gemm_mma<128, false, true><<<dim3(VG, 2), 256, SMN128>>>(p_cat, p_bwh + 196608, p_bwl + 196608, bl1, p_h1, NN, 256, 256);

    // ======================= layer 2 =======================
    // w2 = relu(w1) @ We2 + be2   (relu fused into A split)
    gemm_mma<128, true, false><<<dim3(EG, 2), 256, SMN128>>>(p_w1, p_bwh + 32768, p_bwl + 32768, be2, p_A, NE, 128, 256);

    norm_kernel<HF><<<(NN + 7) / 8, 256>>>(p_h1, p_inv, NN);
    msg_kernel<HF><<<NE / 8, 256>>>(p_h1, p_A, p_A, p_inv, src, dst);   // in-place

    gemm_mma<128, false, true><<<dim3(EG, 2), 256, SMN128>>>(p_A, p_bwh + 65536,  p_bwl + 65536,  br2a, p_B, NE, 256, 256);
    gemm_mma<128, false, true><<<dim3(EG, 2), 256, SMN128>>>(p_B, p_bwh + 131072, p_bwl + 131072, br2b, p_A, NE, 256, 256);

    cudaMemsetAsync(p_hN, 0, (size_t)NN * HF * sizeof(float));
    scatter_kernel<HF><<<NE / 8, 256>>>(p_A, dst, p_hN);
    cat_kernel<HF><<<(NN * 2 * HF + 255) / 256, 256>>>(p_h1, p_hN, p_deg, p_cat, NN);

    gemm_mma<32, false, false><<<dim3(VG, 1), 256, SMN32>>>(p_cat, p_bwh + 262144, p_bwl + 262144, bl2, out, NN, 512, 32);
}

// round 13
// speedup vs baseline: 1.1731x; 1.0179x over previous
#include <cuda_runtime.h>
#include <cuda_bf16.h>
#include <math.h>
#include <stdint.h>

// ---------------------------------------------------------------------------
// Problem constants
// ---------------------------------------------------------------------------
static constexpr int NN = 50000;    // nodes
static constexpr int NE = 800000;   // edges
static constexpr int F1 = 128;      // in_feats
static constexpr int HF = 256;      // h_feats
static constexpr int CF = 32;       // classes

// ---------------------------------------------------------------------------
// Scratch (device globals -- no allocation allowed)
// ---------------------------------------------------------------------------
__device__ __align__(16) float g_w1 [(size_t)NE * F1];      // layer-1 edge weights (kept for layer 2)
__device__ __align__(16) float g_bufA[(size_t)NE * HF];
__device__ __align__(16) float g_bufB[(size_t)NE * HF];
__device__ __align__(16) float g_h1 [(size_t)NN * HF];
__device__ __align__(16) float g_hN [(size_t)NN * HF];
__device__ __align__(16) float g_cat[(size_t)NN * 2 * HF];
__device__ float g_inv[NN];
__device__ float g_cos[NE];
__device__ int   g_deg[NN];

// split-bf16 weights, pre-transposed to [N, K] K-major
// offsets (elements): Wr1a=0(16384) Wr1b=16384 We2=32768(32768)
//                     Wr2a=65536(65536) Wr2b=131072 Wl1=196608(65536) Wl2=262144(16384)
static constexpr size_t WT_TOTAL = 278528;
__device__ __align__(16) __nv_bfloat16 g_bwh[WT_TOTAL];
__device__ __align__(16) __nv_bfloat16 g_bwl[WT_TOTAL];

// ---------------------------------------------------------------------------
// helpers
// ---------------------------------------------------------------------------
__device__ __forceinline__ uint32_t smem_u32(const void* p) {
    uint32_t a;
    asm("{ .reg .u64 t; cvta.to.shared.u64 t, %1; cvt.u32.u64 %0, t; }" : "=r"(a) : "l"(p));
    return a;
}

__device__ __forceinline__ void ldm4(uint32_t& r0, uint32_t& r1, uint32_t& r2, uint32_t& r3,
                                     uint32_t addr) {
    asm volatile("ldmatrix.sync.aligned.m8n8.x4.shared.b16 {%0,%1,%2,%3}, [%4];"
                 : "=r"(r0), "=r"(r1), "=r"(r2), "=r"(r3) : "r"(addr));
}

__device__ __forceinline__ void mma16816(float* c, const uint32_t* a, const uint32_t* b) {
    asm volatile("mma.sync.aligned.m16n8k16.row.col.f32.bf16.bf16.f32 "
                 "{%0,%1,%2,%3}, {%4,%5,%6,%7}, {%8,%9}, {%0,%1,%2,%3};"
                 : "+f"(c[0]), "+f"(c[1]), "+f"(c[2]), "+f"(c[3])
                 : "r"(a[0]), "r"(a[1]), "r"(a[2]), "r"(a[3]), "r"(b[0]), "r"(b[1]));
}

// split one fp32 pair into packed bf16 hi + bf16 lo (exact residual then rounded)
__device__ __forceinline__ uint32_t split2(float a, float b, uint32_t& lo) {
    __nv_bfloat16 ha = __float2bfloat16(a), hb = __float2bfloat16(b);
    float ra = a - __bfloat162float(ha);
    float rb = b - __bfloat162float(hb);
    __nv_bfloat16 la = __float2bfloat16(ra), lb = __float2bfloat16(rb);
    lo = (uint32_t)__bfloat16_as_ushort(la) | ((uint32_t)__bfloat16_as_ushort(lb) << 16);
    return (uint32_t)__bfloat16_as_ushort(ha) | ((uint32_t)__bfloat16_as_ushort(hb) << 16);
}

// ---------------------------------------------------------------------------
// Weight pre-transform: W[K,N] fp32 -> Bt_hi/Bt_lo [N,K] bf16
// ---------------------------------------------------------------------------
__global__ void conv_w_kernel(const float* __restrict__ W, int K, int N,
                              __nv_bfloat16* __restrict__ hi, __nv_bfloat16* __restrict__ lo)
{
    const int idx = blockIdx.x * 256 + threadIdx.x;
    if (idx >= K * N) return;
    const int k = idx / N;
    const int n = idx - k * N;
    const float x = W[idx];
    const __nv_bfloat16 h = __float2bfloat16(x);
    const float r = x - __bfloat162float(h);
    hi[(size_t)n * K + k] = h;
    lo[(size_t)n * K + k] = __float2bfloat16(r);
}

// ---------------------------------------------------------------------------
// bf16 split-3 GEMM via mma.sync.m16n8k16 + cp.async A staging.
//   C = act_out( act_in(A) @ B + bias )  with optional fused epilogues:
//   MSG_OUT:     C[gm,:] = cosv[gm] * (A@B+bias) * hfeat[src[gm],:]
//   SCATTER_OUT: hN[dst[gm],:] += relu(A@B+bias)   (red.global.add.v2)
// ---------------------------------------------------------------------------
template<int CTA_N, bool RELU_IN, bool RELU_OUT, bool MSG_OUT, bool SCATTER_OUT>
__launch_bounds__(256, 2)
__global__ void gemm_mma(const float* __restrict__ A,
                         const __nv_bfloat16* __restrict__ Bh,
                         const __nv_bfloat16* __restrict__ Bl,
                         const float* __restrict__ bias,
                         float* __restrict__ C,
                         int M, int K, int N,
                         const float* __restrict__ cosv,
                         const float* __restrict__ hfeat,
                         const int* __restrict__ src,
                         const int* __restrict__ dst)
{
    extern __shared__ char sm[];
    constexpr int RS    = 144;
    constexpr int S_AHI = 0;
    constexpr int S_ALO = 128 * RS;
    constexpr int S_BHI = 2 * 128 * RS;
    constexpr int S_BLO = S_BHI + CTA_N * RS;
    constexpr int S_STG = S_BHI + 2 * CTA_N * RS;  // fp32 A staging: 32768 B
    constexpr int SPAN  = CTA_N / 2;
    constexpr int NI    = SPAN / 8;

    const int tid    = threadIdx.x;
    const int lane   = tid & 31;
    const int warp   = tid >> 5;
    const int warp_m = warp & 3;
    const int warp_n = warp >> 2;
    const int m0     = blockIdx.x * 128;
    const int n0     = blockIdx.y * CTA_N;

    const uint32_t sb = smem_u32(sm);
    const uint32_t lmo = ((lane & 7) + ((lane >> 3) & 1) * 8) * RS + (lane >> 4) * 16;
    const uint32_t a_base = sb + S_AHI + (uint32_t)(warp_m * 32) * RS + lmo;
    const uint32_t b_base = sb + S_BHI + (uint32_t)(warp_n * SPAN) * RS + lmo;

    float acc[2][NI][4];
    #pragma unroll
    for (int mi = 0; mi < 2; mi++)
        #pragma unroll
        for (int ni = 0; ni < NI; ni++)
            #pragma unroll
            for (int c = 0; c < 4; c++) acc[mi][ni][c] = 0.f;

    auto cp_stage = [&](int kc) {
        #pragma unroll
        for (int i = 0; i < 8; i++) {
            const int slot = tid + i * 256;
            const int row  = slot >> 4;
            const int c4   = slot & 15;
            const int gm   = m0 + row;
            const bool ok  = (gm < M);
            const float* gp = A + (size_t)(ok ? gm : m0) * K + kc * 64 + c4 * 4;
            const uint32_t dp = sb + S_STG + (uint32_t)slot * 16;
            const int ssz = ok ? 16 : 0;
            asm volatile("cp.async.cg.shared.global [%0], [%1], 16, %2;"
                         :: "r"(dp), "l"(gp), "r"(ssz) : "memory");
        }
        asm volatile("cp.async.commit_group;" ::: "memory");
    };

    const int NC = K >> 6;
    cp_stage(0);
    asm volatile("cp.async.wait_group 0;" ::: "memory");
    __syncthreads();

    for (int kc = 0; kc < NC; kc++) {
        // ---- convert staged fp32 chunk -> split bf16 hi/lo ----
        #pragma unroll
        for (int i = 0; i < 8; i++) {
            const int slot = tid + i * 256;
            const int row  = slot >> 4;
            const int c4   = slot & 15;
            float4 v = *reinterpret_cast<const float4*>(sm + S_STG + (size_t)slot * 16);
            if (RELU_IN) {
                v.x = fmaxf(v.x, 0.f); v.y = fmaxf(v.y, 0.f);
                v.z = fmaxf(v.z, 0.f); v.w = fmaxf(v.w, 0.f);
            }
            uint32_t l0, l1;
            const uint32_t h0 = split2(v.x, v.y, l0);
            const uint32_t h1 = split2(v.z, v.w, l1);
            const int off = row * RS + c4 * 8;
            *reinterpret_cast<uint2*>(sm + S_AHI + off) = make_uint2(h0, h1);
            *reinterpret_cast<uint2*>(sm + S_ALO + off) = make_uint2(l0, l1);
        }
        // ---- B chunk (L2-hot weights) ----
        #pragma unroll
        for (int i = 0; i < CTA_N / 32; i++) {
            const int slot = tid + i * 256;
            const int n    = slot >> 3;
            const int grp  = slot & 7;
            const size_t go = (size_t)(n0 + n) * K + kc * 64 + grp * 8;
            const uint4 vh = *reinterpret_cast<const uint4*>(Bh + go);
            const uint4 vl = *reinterpret_cast<const uint4*>(Bl + go);
            const int off = n * RS + grp * 16;
            *reinterpret_cast<uint4*>(sm + S_BHI + off) = vh;
            *reinterpret_cast<uint4*>(sm + S_BLO + off) = vl;
        }
        __syncthreads();

        if (kc + 1 < NC) cp_stage(kc + 1);

        // ---- 3 split terms ----
        #pragma unroll
        for (int s = 0; s < 3; s++) {
            const uint32_t ab = a_base + ((s == 2) ? (uint32_t)(S_ALO - S_AHI) : 0u);
            const uint32_t bb = b_base + ((s == 1) ? (uint32_t)(CTA_N * RS)    : 0u);
            #pragma unroll
            for (int ks = 0; ks < 4; ks++) {
                uint32_t a[2][4];
                ldm4(a[0][0], a[0][1], a[0][2], a[0][3], ab + ks * 32);
                ldm4(a[1][0], a[1][1], a[1][2], a[1][3], ab + 16 * RS + ks * 32);
                uint32_t b[NI][2];
                #pragma unroll
                for (int p = 0; p < NI / 2; p++) {
                    uint32_t r0, r1, r2, r3;
                    ldm4(r0, r1, r2, r3, bb + (uint32_t)(p * 16) * RS + ks * 32);
                    b[2 * p][0] = r0; b[2 * p + 1][0] = r1;
                    b[2 * p][1] = r2; b[2 * p + 1][1] = r3;
                }
                #pragma unroll
                for (int mi = 0; mi < 2; mi++)
                    #pragma unroll
                    for (int ni = 0; ni < NI; ni++)
                        mma16816(acc[mi][ni], a[mi], b[ni]);
            }
        }
        asm volatile("cp.async.wait_group 0;" ::: "memory");
        __syncthreads();
    }

    // ---- epilogue ----
    const int g = lane >> 2;
    const int t = lane & 3;
    #pragma unroll
    for (int mi = 0; mi < 2; mi++) {
        const int gm = m0 + warp_m * 32 + mi * 16 + g;
        int s0 = 0, s1 = 0, d0 = 0, d1 = 0;
        float c0 = 0.f, c1 = 0.f;
        if (MSG_OUT) {
            if (gm < M)     { s0 = src[gm];     c0 = cosv[gm]; }
            if (gm + 8 < M) { s1 = src[gm + 8]; c1 = cosv[gm + 8]; }
        }
        if (SCATTER_OUT) {
            if (gm < M)     d0 = dst[gm];
            if (gm + 8 < M) d1 = dst[gm + 8];
        }
        #pragma unroll
        for (int ni = 0; ni < NI; ni++) {
            const int gn = n0 + warp_n * SPAN + ni * 8 + t * 2;
            const float2 bb = *reinterpret_cast<const float2*>(bias + gn);
            if (gm < M) {
                float2 o = make_float2(acc[mi][ni][0] + bb.x, acc[mi][ni][1] + bb.y);
                if (RELU_OUT) { o.x = fmaxf(o.x, 0.f); o.y = fmaxf(o.y, 0.f); }
                if (MSG_OUT) {
                    const float2 hv = *reinterpret_cast<const float2*>(hfeat + (size_t)s0 * N + gn);
                    o.x = c0 * o.x * hv.x; o.y = c0 * o.y * hv.y;
                }
                if (SCATTER_OUT) {
                    asm volatile("red.global.add.v2.f32 [%0], {%1, %2};"
                                 :: "l"(C + (size_t)d0 * N + gn), "f"(o.x), "f"(o.y) : "memory");
                } else {
                    *reinterpret_cast<float2*>(C + (size_t)gm * N + gn) = o;
                }
            }
            if (gm + 8 < M) {
                float2 o = make_float2(acc[mi][ni][2] + bb.x, acc[mi][ni][3] + bb.y);
                if (RELU_OUT) { o.x = fmaxf(o.x, 0.f); o.y = fmaxf(o.y, 0.f); }
                if (MSG_OUT) {
                    const float2 hv = *reinterpret_cast<const float2*>(hfeat + (size_t)s1 * N + gn);
                    o.x = c1 * o.x * hv.x; o.y = c1 * o.y * hv.y;
                }
                if (SCATTER_OUT) {
                    asm volatile("red.global.add.v2.f32 [%0], {%1, %2};"
                                 :: "l"(C + (size_t)d1 * N + gn), "f"(o.x), "f"(o.y) : "memory");
                } else {
                    *reinterpret_cast<float2*>(C + (size_t)(gm + 8) * N + gn) = o;
                }
            }
        }
    }
}

// ---------------------------------------------------------------------------
// per-edge cosine: cos[e] = dot(h[s],h[d]) * inv[s] * inv[d]   (warp/edge)
// ---------------------------------------------------------------------------
template<int F>
__global__ void cos_kernel(const float* __restrict__ h,
                           const float* __restrict__ invn,
                           const int* __restrict__ src,
                           const int* __restrict__ dst,
                           float* __restrict__ cosv)
{
    const int e    = blockIdx.x * 8 + (threadIdx.x >> 5);
    const int lane = threadIdx.x & 31;
    const int s = src[e];
    const int d = dst[e];
    const float4* hs4 = reinterpret_cast<const float4*>(h + (size_t)s * F);
    const float4* hd4 = reinterpret_cast<const float4*>(h + (size_t)d * F);
    float dot = 0.f;
    #pragma unroll
    for (int j = 0; j < F / 128; j++) {
        const float4 a = hs4[lane + j * 32];
        const float4 b = hd4[lane + j * 32];
        dot += a.x * b.x + a.y * b.y + a.z * b.z + a.w * b.w;
    }
    #pragma unroll
    for (int o = 16; o > 0; o >>= 1) dot += __shfl_xor_sync(0xFFFFFFFFu, dot, o);
    if (lane == 0) cosv[e] = dot * invn[s] * invn[d];
}

// ---------------------------------------------------------------------------
// w1 + msg1 fused: w1[e,j] = ef@We1+be1;  m[e,j] = cos[e]*w1[e,j]*nf[src[e],j]
// (128 threads per edge -> src/cos loads broadcast, nf gather coalesced)
// ---------------------------------------------------------------------------
__global__ void w1msg_kernel(const float* __restrict__ ef, const float* __restrict__ We,
                             const float* __restrict__ be,
                             const int* __restrict__ src,
                             const float* __restrict__ cosv,
                             const float* __restrict__ nf,
                             float* __restrict__ w1, float* __restrict__ m)
{
    const int idx = blockIdx.x * 256 + threadIdx.x;
    const int e = idx >> 7;
    const int j = idx & 127;
    const float e0 = ef[2 * e];
    const float e1 = ef[2 * e + 1];
    const float w = fmaf(e1, We[128 + j], fmaf(e0, We[j], be[j]));
    w1[idx] = w;
    m[idx] = cosv[e] * w * nf[(size_t)src[e] * 128 + j];
}

// ---------------------------------------------------------------------------
// per-node inverse norm
// ---------------------------------------------------------------------------
template<int F>
__global__ void norm_kernel(const float* __restrict__ h, float* __restrict__ invn,
                            int n_nodes)
{
    const int n = blockIdx.x * 8 + (threadIdx.x >> 5);
    if (n >= n_nodes) return;
    const int lane = threadIdx.x & 31;
    const float4* h4 = reinterpret_cast<const float4*>(h + (size_t)n * F);
    float ss = 0.f;
    #pragma unroll
    for (int j = 0; j < F / 128; j++) {
        float4 v = h4[lane + j * 32];
        ss += v.x * v.x + v.y * v.y + v.z * v.z + v.w * v.w;
    }
    #pragma unroll
    for (int o = 16; o > 0; o >>= 1) ss += __shfl_xor_sync(0xFFFFFFFFu, ss, o);
    if (lane == 0) invn[n] = 1.f / fmaxf(sqrtf(ss), 1e-12f);
}

// ---------------------------------------------------------------------------
// degree
// ---------------------------------------------------------------------------
__global__ void deg_kernel(const int* __restrict__ dst, int* __restrict__ deg)
{
    const int e = blockIdx.x * 256 + threadIdx.x;
    if (e < NE) atomicAdd(&deg[dst[e]], 1);
}

// ---------------------------------------------------------------------------
// cat[n, 0:F] = h; cat[n, F:2F] = hN / max(deg, 1)
// ---------------------------------------------------------------------------
template<int F>
__global__ void cat_kernel(const float* __restrict__ h,
                           const float* __restrict__ hN,
                           const int* __restrict__ deg,
                           float* __restrict__ out, int n_nodes)
{
    const int idx = blockIdx.x * 256 + threadIdx.x;
    if (idx >= n_nodes * 2 * F) return;
    const int n = idx / (2 * F);
    const int k = idx - n * 2 * F;
    float v;
    if (k < F) v = h[(size_t)n * F + k];
    else       v = hN[(size_t)n * F + (k - F)] / fmaxf((float)deg[n], 1.f);
    out[idx] = v;
}

// ---------------------------------------------------------------------------
// launch
// ---------------------------------------------------------------------------
extern "C" void kernel_launch(void* const* d_in, const int* in_sizes, int n_in,
                              void* d_out, int out_size)
{
    (void)in_sizes; (void)n_in; (void)out_size;

    const float* nf   = (const float*)d_in[0];
    const float* ef   = (const float*)d_in[1];
    const int*   src  = (const int*)  d_in[2];
    const int*   dst  = (const int*)  d_in[3];
    const float* We1  = (const float*)d_in[4];
    const float* be1  = (const float*)d_in[5];
    const float* Wr1a = (const float*)d_in[6];
    const float* br1a = (const float*)d_in[7];
    const float* Wr1b = (const float*)d_in[8];
    const float* br1b = (const float*)d_in[9];
    const float* Wl1  = (const float*)d_in[10];
    const float* bl1  = (const float*)d_in[11];
    const float* We2  = (const float*)d_in[12];
    const float* be2  = (const float*)d_in[13];
    const float* Wr2a = (const float*)d_in[14];
    const float* br2a = (const float*)d_in[15];
    const float* Wr2b = (const float*)d_in[16];
    const float* br2b = (const float*)d_in[17];
    const float* Wl2  = (const float*)d_in[18];
    const float* bl2  = (const float*)d_in[19];
    float* out = (float*)d_out;

    float *p_w1, *p_A, *p_B, *p_h1, *p_hN, *p_cat, *p_inv, *p_cos;
    int*   p_deg;
    __nv_bfloat16 *p_bwh, *p_bwl;
    cudaGetSymbolAddress((void**)&p_w1,  g_w1);
    cudaGetSymbolAddress((void**)&p_A,   g_bufA);
    cudaGetSymbolAddress((void**)&p_B,   g_bufB);
    cudaGetSymbolAddress((void**)&p_h1,  g_h1);
    cudaGetSymbolAddress((void**)&p_hN,  g_hN);
    cudaGetSymbolAddress((void**)&p_cat, g_cat);
    cudaGetSymbolAddress((void**)&p_inv, g_inv);
    cudaGetSymbolAddress((void**)&p_cos, g_cos);
    cudaGetSymbolAddress((void**)&p_deg, g_deg);
    cudaGetSymbolAddress((void**)&p_bwh, g_bwh);
    cudaGetSymbolAddress((void**)&p_bwl, g_bwl);

    // dynamic SMEM: 2*128*144 (A) + 2*CTA_N*144 (B) + 32768 (fp32 A stage)
    constexpr int SMN128 = 36864 + 128 * 288 + 32768;   // 106496 -> 2 CTAs/SM
    constexpr int SMN32  = 36864 + 32  * 288 + 32768;   // 78848
    cudaFuncSetAttribute(gemm_mma<128, false, true,  false, false>, cudaFuncAttributeMaxDynamicSharedMemorySize, SMN128);
    cudaFuncSetAttribute(gemm_mma<128, false, true,  false, true >, cudaFuncAttributeMaxDynamicSharedMemorySize, SMN128);
    cudaFuncSetAttribute(gemm_mma<128, true,  false, true,  false>, cudaFuncAttributeMaxDynamicSharedMemorySize, SMN128);
    cudaFuncSetAttribute(gemm_mma<32,  false, false, false, false>, cudaFuncAttributeMaxDynamicSharedMemorySize, SMN32);

    const int EG = NE / 128;              // 6250 edge M-tiles
    const int VG = (NN + 127) / 128;      // 391 node M-tiles

    // ---- zero accumulators first ----
    cudaMemsetAsync(p_deg, 0, NN * sizeof(int));
    cudaMemsetAsync(p_hN, 0, (size_t)NN * F1 * sizeof(float));

    // ---- prep: weight splits, norms, cosines, fused w1+msg1 ----
    conv_w_kernel<<<(128 * 128 + 255) / 256, 256>>>(Wr1a, 128, 128, p_bwh + 0,     p_bwl + 0);
    conv_w_kernel<<<(128 * 128 + 255) / 256, 256>>>(Wr1b, 128, 128, p_bwh + 16384, p_bwl + 16384);
    norm_kernel<F1><<<(NN + 7) / 8, 256>>>(nf, p_inv, NN);
    cos_kernel<F1><<<NE / 8, 256>>>(nf, p_inv, src, dst, p_cos);
    w1msg_kernel<<<(NE * F1) / 256, 256>>>(ef, We1, be1, src, p_cos, nf, p_w1, p_A);
    deg_kernel<<<(NE + 255) / 256, 256>>>(dst, p_deg);

    // ======================= layer 1 =======================
    gemm_mma<128, false, true, false, false><<<dim3(EG, 1), 256, SMN128>>>(
        p_A, p_bwh + 0, p_bwl + 0, br1a, p_B, NE, 128, 128,
        nullptr, nullptr, nullptr, nullptr);

    // G1b + fused scatter: hN[dst] += relu(r1 @ Wr1b + br1b)
    gemm_mma<128, false, true, false, true><<<dim3(EG, 1), 256, SMN128>>>(
        p_B, p_bwh + 16384, p_bwl + 16384, br1b, p_hN, NE, 128, 128,
        nullptr, nullptr, nullptr, dst);

    // remaining weight pre-splits (independent)
    conv_w_kernel<<<(128 * 256 + 255) / 256, 256>>>(We2,  128, 256, p_bwh + 32768,  p_bwl + 32768);
    conv_w_kernel<<<(256 * 256 + 255) / 256, 256>>>(Wr2a, 256, 256, p_bwh + 65536,  p_bwl + 65536);
    conv_w_kernel<<<(256 * 256 + 255) / 256, 256>>>(Wr2b, 256, 256, p_bwh + 131072, p_bwl + 131072);
    conv_w_kernel<<<(256 * 256 + 255) / 256, 256>>>(Wl1,  256, 256, p_bwh + 196608, p_bwl + 196608);
    conv_w_kernel<<<(512 * 32  + 255) / 256, 256>>>(Wl2,  512, 32,  p_bwh + 262144, p_bwl + 262144);

    cat_kernel<F1><<<(NN * 2 * F1 + 255) / 256, 256>>>(nf, p_hN, p_deg, p_cat, NN);

    gemm_mma<128, false, true, false, false><<<dim3(VG, 2), 256, SMN128>>>(
        p_cat, p_bwh + 196608, p_bwl + 196608, bl1, p_h1, NN, 256, 256,
        nullptr, nullptr, nullptr, nullptr);

    // ======================= layer 2 =======================
    norm_kernel<HF><<<(NN + 7) / 8, 256>>>(p_h1, p_inv, NN);
    cos_kernel<HF><<<NE / 8, 256>>>(p_h1, p_inv, src, dst, p_cos);
    cudaMemsetAsync(p_hN, 0, (size_t)NN * HF * sizeof(float));

    // Ge2 + fused msg2: m2 = cos * (relu(w1) @ We2 + be2) * h1[src]
    gemm_mma<128, true, false, true, false><<<dim3(EG, 2), 256, SMN128>>>(
        p_w1, p_bwh + 32768, p_bwl + 32768, be2, p_A, NE, 128, 256,
        p_cos, p_h1, src, nullptr);

    gemm_mma<128, false, true, false, false><<<dim3(EG, 2), 256, SMN128>>>(
        p_A, p_bwh + 65536, p_bwl + 65536, br2a, p_B, NE, 256, 256,
        nullptr, nullptr, nullptr, nullptr);

    // G2b + fused scatter: hN[dst] += relu(r1 @ Wr2b + br2b)
    gemm_mma<128, false, true, false, true><<<dim3(EG, 2), 256, SMN128>>>(
        p_B, p_bwh + 131072, p_bwl + 131072, br2b, p_hN, NE, 256, 256,
        nullptr, nullptr, nullptr, dst);

    cat_kernel<HF><<<(NN * 2 * HF + 255) / 256, 256>>>(p_h1, p_hN, p_deg, p_cat, NN);

    gemm_mma<32, false, false, false, false><<<dim3(VG, 1), 256, SMN32>>>(
        p_cat, p_bwh + 262144, p_bwl + 262144, bl2, out, NN, 512, 32,
        nullptr, nullptr, nullptr, nullptr);
}

// round 15
// speedup vs baseline: 1.2403x; 1.0573x over previous
#include <cuda_runtime.h>
#include <cuda_bf16.h>
#include <math.h>
#include <stdint.h>

// ---------------------------------------------------------------------------
// Problem constants
// ---------------------------------------------------------------------------
static constexpr int NN = 50000;    // nodes
static constexpr int NE = 800000;   // edges
static constexpr int F1 = 128;      // in_feats
static constexpr int HF = 256;      // h_feats
static constexpr int CF = 32;       // classes

// ---------------------------------------------------------------------------
// Scratch (device globals -- no allocation allowed)
// ---------------------------------------------------------------------------
// split-bf16 edge matrices (ping/pong) + relu(w1) split
__device__ __align__(16) __nv_bfloat16 g_p1h[(size_t)NE * HF];
__device__ __align__(16) __nv_bfloat16 g_p1l[(size_t)NE * HF];
__device__ __align__(16) __nv_bfloat16 g_p2h[(size_t)NE * HF];
__device__ __align__(16) __nv_bfloat16 g_p2l[(size_t)NE * HF];
__device__ __align__(16) __nv_bfloat16 g_rwh[(size_t)NE * F1];
__device__ __align__(16) __nv_bfloat16 g_rwl[(size_t)NE * F1];

__device__ __align__(16) float g_h1 [(size_t)NN * HF];
__device__ __align__(16) float g_hN [(size_t)NN * HF];
__device__ __align__(16) float g_cat[(size_t)NN * 2 * HF];
__device__ float g_inv[NN];
__device__ float g_cos[NE];
__device__ int   g_deg[NN];

// split-bf16 weights, pre-transposed to [N, K] K-major
static constexpr size_t WT_TOTAL = 278528;
__device__ __align__(16) __nv_bfloat16 g_bwh[WT_TOTAL];
__device__ __align__(16) __nv_bfloat16 g_bwl[WT_TOTAL];

// ---------------------------------------------------------------------------
// helpers
// ---------------------------------------------------------------------------
__device__ __forceinline__ uint32_t smem_u32(const void* p) {
    uint32_t a;
    asm("{ .reg .u64 t; cvta.to.shared.u64 t, %1; cvt.u32.u64 %0, t; }" : "=r"(a) : "l"(p));
    return a;
}

__device__ __forceinline__ void ldm4(uint32_t& r0, uint32_t& r1, uint32_t& r2, uint32_t& r3,
                                     uint32_t addr) {
    asm volatile("ldmatrix.sync.aligned.m8n8.x4.shared.b16 {%0,%1,%2,%3}, [%4];"
                 : "=r"(r0), "=r"(r1), "=r"(r2), "=r"(r3) : "r"(addr));
}

__device__ __forceinline__ void mma16816(float* c, const uint32_t* a, const uint32_t* b) {
    asm volatile("mma.sync.aligned.m16n8k16.row.col.f32.bf16.bf16.f32 "
                 "{%0,%1,%2,%3}, {%4,%5,%6,%7}, {%8,%9}, {%0,%1,%2,%3};"
                 : "+f"(c[0]), "+f"(c[1]), "+f"(c[2]), "+f"(c[3])
                 : "r"(a[0]), "r"(a[1]), "r"(a[2]), "r"(a[3]), "r"(b[0]), "r"(b[1]));
}

// split one fp32 pair into packed bf16 hi + bf16 lo (fp32 A path only)
__device__ __forceinline__ uint32_t split2(float a, float b, uint32_t& lo) {
    __nv_bfloat16 ha = __float2bfloat16(a), hb = __float2bfloat16(b);
    float ra = a - __bfloat162float(ha);
    float rb = b - __bfloat162float(hb);
    __nv_bfloat16 la = __float2bfloat16(ra), lb = __float2bfloat16(rb);
    lo = (uint32_t)__bfloat16_as_ushort(la) | ((uint32_t)__bfloat16_as_ushort(lb) << 16);
    return (uint32_t)__bfloat16_as_ushort(ha) | ((uint32_t)__bfloat16_as_ushort(hb) << 16);
}

// pack float2 -> bf16x2 (x in low half, y in high half)
__device__ __forceinline__ uint32_t pack_bf16x2(float x, float y) {
    uint32_t r;
    asm("cvt.rn.bf16x2.f32 %0, %1, %2;" : "=r"(r) : "f"(y), "f"(x));
    return r;
}

// ---------------------------------------------------------------------------
// Weight pre-transform: W[K,N] fp32 -> Bt_hi/Bt_lo [N,K] bf16
// ---------------------------------------------------------------------------
__global__ void conv_w_kernel(const float* __restrict__ W, int K, int N,
                              __nv_bfloat16* __restrict__ hi, __nv_bfloat16* __restrict__ lo)
{
    const int idx = blockIdx.x * 256 + threadIdx.x;
    if (idx >= K * N) return;
    const int k = idx / N;
    const int n = idx - k * N;
    const float x = W[idx];
    const __nv_bfloat16 h = __float2bfloat16(x);
    const float r = x - __bfloat162float(h);
    hi[(size_t)n * K + k] = h;
    lo[(size_t)n * K + k] = __float2bfloat16(r);
}

// ---------------------------------------------------------------------------
// bf16 split-3 GEMM via mma.sync.m16n8k16.
// A_BF16=true : A pre-split bf16 hi/lo [M,K]; cp.async double-buffered tiles,
//               no convert on the critical path.
// A_BF16=false: A fp32 [M,K]; cp.async stage + in-SMEM split (node GEMMs).
// Epilogue: bias (+relu) (+msg: cos*o*hfeat[src]) then
//   SCATTER_OUT: red.global.add.v2 into C[dst[gm],:], else
//   OUT_SPLIT:   write split bf16 pairs to Ch/Cl, else plain fp32 store to C.
// ---------------------------------------------------------------------------
template<int CTA_N, bool A_BF16, bool RELU_OUT, bool MSG_OUT, bool SCATTER_OUT, bool OUT_SPLIT>
__launch_bounds__(256, 2)
__global__ void gemm_mma(const float* __restrict__ Af,
                         const __nv_bfloat16* __restrict__ Ah,
                         const __nv_bfloat16* __restrict__ Al,
                         const __nv_bfloat16* __restrict__ Bh,
                         const __nv_bfloat16* __restrict__ Bl,
                         const float* __restrict__ bias,
                         float* __restrict__ C,
                         __nv_bfloat16* __restrict__ Ch,
                         __nv_bfloat16* __restrict__ Cl,
                         int M, int K, int N,
                         const float* __restrict__ cosv,
                         const float* __restrict__ hfeat,
                         const int* __restrict__ src,
                         const int* __restrict__ dst)
{
    extern __shared__ char sm[];
    constexpr int RS   = 144;                  // SMEM row stride bytes
    constexpr int AT   = 128 * RS;             // one A part (hi or lo): 18432
    constexpr int S_B  = A_BF16 ? 4 * AT : 2 * AT;
    constexpr int S_STG = S_B + 2 * CTA_N * RS;   // fp32 path staging
    constexpr int SPAN = CTA_N / 2;
    constexpr int NI   = SPAN / 8;

    const int tid    = threadIdx.x;
    const int lane   = tid & 31;
    const int warp   = tid >> 5;
    const int warp_m = warp & 3;
    const int warp_n = warp >> 2;
    const int m0     = blockIdx.x * 128;
    const int n0     = blockIdx.y * CTA_N;

    const uint32_t sb = smem_u32(sm);
    const uint32_t lmo = ((lane & 7) + ((lane >> 3) & 1) * 8) * RS + (lane >> 4) * 16;
    const uint32_t b_base = sb + S_B + (uint32_t)(warp_n * SPAN) * RS + lmo;
    const uint32_t a_off  = (uint32_t)(warp_m * 32) * RS + lmo;

    float acc[2][NI][4];
    #pragma unroll
    for (int mi = 0; mi < 2; mi++)
        #pragma unroll
        for (int ni = 0; ni < NI; ni++)
            #pragma unroll
            for (int c = 0; c < 4; c++) acc[mi][ni][c] = 0.f;

    // ---- shared B-tile loader ----
    auto load_b = [&](int kc) {
        #pragma unroll
        for (int i = 0; i < CTA_N / 32; i++) {
            const int slot = tid + i * 256;
            const int n    = slot >> 3;
            const int grp  = slot & 7;
            const size_t go = (size_t)(n0 + n) * K + kc * 64 + grp * 8;
            const uint4 vh = *reinterpret_cast<const uint4*>(Bh + go);
            const uint4 vl = *reinterpret_cast<const uint4*>(Bl + go);
            const int off = n * RS + grp * 16;
            *reinterpret_cast<uint4*>(sm + S_B + off) = vh;
            *reinterpret_cast<uint4*>(sm + S_B + CTA_N * RS + off) = vl;
        }
    };

    // ---- MMA over one A buffer ----
    auto do_mma = [&](uint32_t abase) {
        #pragma unroll
        for (int s = 0; s < 3; s++) {
            const uint32_t ab = abase + ((s == 2) ? (uint32_t)AT : 0u);
            const uint32_t bb = b_base + ((s == 1) ? (uint32_t)(CTA_N * RS) : 0u);
            #pragma unroll
            for (int ks = 0; ks < 4; ks++) {
                uint32_t a[2][4];
                ldm4(a[0][0], a[0][1], a[0][2], a[0][3], ab + ks * 32);
                ldm4(a[1][0], a[1][1], a[1][2], a[1][3], ab + 16 * RS + ks * 32);
                uint32_t b[NI][2];
                #pragma unroll
                for (int p = 0; p < NI / 2; p++) {
                    uint32_t r0, r1, r2, r3;
                    ldm4(r0, r1, r2, r3, bb + (uint32_t)(p * 16) * RS + ks * 32);
                    b[2 * p][0] = r0; b[2 * p + 1][0] = r1;
                    b[2 * p][1] = r2; b[2 * p + 1][1] = r3;
                }
                #pragma unroll
                for (int mi = 0; mi < 2; mi++)
                    #pragma unroll
                    for (int ni = 0; ni < NI; ni++)
                        mma16816(acc[mi][ni], a[mi], b[ni]);
            }
        }
    };

    const int NC = K >> 6;

    if constexpr (A_BF16) {
        // ---------- direct bf16 A path: double-buffered cp.async tiles ----------
        auto cp_a = [&](int kc, int buf) {
            #pragma unroll
            for (int i = 0; i < 4; i++) {
                const int slot = tid + i * 256;      // 0..1023
                const int row  = slot >> 3;
                const int grp  = slot & 7;
                const int gm   = m0 + row;
                const bool ok  = (gm < M);
                const size_t go = (size_t)(ok ? gm : m0) * K + kc * 64 + grp * 8;
                const uint32_t dh = sb + (uint32_t)(buf * 2 * AT) + (uint32_t)(row * RS + grp * 16);
                const int ssz = ok ? 16 : 0;
                asm volatile("cp.async.cg.shared.global [%0], [%1], 16, %2;"
                             :: "r"(dh), "l"(Ah + go), "r"(ssz) : "memory");
                asm volatile("cp.async.cg.shared.global [%0], [%1], 16, %2;"
                             :: "r"(dh + AT), "l"(Al + go), "r"(ssz) : "memory");
            }
            asm volatile("cp.async.commit_group;" ::: "memory");
        };

        int buf = 0;
        cp_a(0, 0);
        for (int kc = 0; kc < NC; kc++) {
            if (kc + 1 < NC) cp_a(kc + 1, buf ^ 1);
            load_b(kc);
            if (kc + 1 < NC) asm volatile("cp.async.wait_group 1;" ::: "memory");
            else             asm volatile("cp.async.wait_group 0;" ::: "memory");
            __syncthreads();
            do_mma(sb + (uint32_t)(buf * 2 * AT) + a_off);
            __syncthreads();
            buf ^= 1;
        }
    } else {
        // ---------- fp32 A path: stage + convert (node GEMMs only) ----------
        auto cp_stage = [&](int kc) {
            #pragma unroll
            for (int i = 0; i < 8; i++) {
                const int slot = tid + i * 256;
                const int row  = slot >> 4;
                const int c4   = slot & 15;
                const int gm   = m0 + row;
                const bool ok  = (gm < M);
                const float* gp = Af + (size_t)(ok ? gm : m0) * K + kc * 64 + c4 * 4;
                const uint32_t dp = sb + S_STG + (uint32_t)slot * 16;
                const int ssz = ok ? 16 : 0;
                asm volatile("cp.async.cg.shared.global [%0], [%1], 16, %2;"
                             :: "r"(dp), "l"(gp), "r"(ssz) : "memory");
            }
            asm volatile("cp.async.commit_group;" ::: "memory");
        };

        cp_stage(0);
        asm volatile("cp.async.wait_group 0;" ::: "memory");
        __syncthreads();
        for (int kc = 0; kc < NC; kc++) {
            #pragma unroll
            for (int i = 0; i < 8; i++) {
                const int slot = tid + i * 256;
                const int row  = slot >> 4;
                const int c4   = slot & 15;
                float4 v = *reinterpret_cast<const float4*>(sm + S_STG + (size_t)slot * 16);
                uint32_t l0, l1;
                const uint32_t h0 = split2(v.x, v.y, l0);
                const uint32_t h1 = split2(v.z, v.w, l1);
                const int off = row * RS + c4 * 8;
                *reinterpret_cast<uint2*>(sm + off) = make_uint2(h0, h1);
                *reinterpret_cast<uint2*>(sm + AT + off) = make_uint2(l0, l1);
            }
            load_b(kc);
            __syncthreads();
            if (kc + 1 < NC) cp_stage(kc + 1);
            do_mma(sb + a_off);
            asm volatile("cp.async.wait_group 0;" ::: "memory");
            __syncthreads();
        }
    }

    // ---- epilogue ----
    const int g = lane >> 2;
    const int t = lane & 3;
    #pragma unroll
    for (int mi = 0; mi < 2; mi++) {
        const int gm = m0 + warp_m * 32 + mi * 16 + g;
        int s0 = 0, s1 = 0, d0 = 0, d1 = 0;
        float c0 = 0.f, c1 = 0.f;
        if (MSG_OUT) {
            if (gm < M)     { s0 = src[gm];     c0 = cosv[gm]; }
            if (gm + 8 < M) { s1 = src[gm + 8]; c1 = cosv[gm + 8]; }
        }
        if (SCATTER_OUT) {
            if (gm < M)     d0 = dst[gm];
            if (gm + 8 < M) d1 = dst[gm + 8];
        }
        #pragma unroll
        for (int ni = 0; ni < NI; ni++) {
            const int gn = n0 + warp_n * SPAN + ni * 8 + t * 2;
            const float2 bb = *reinterpret_cast<const float2*>(bias + gn);
            #pragma unroll
            for (int half = 0; half < 2; half++) {
                const int gmr = gm + half * 8;
                if (gmr >= M) continue;
                float2 o = make_float2(acc[mi][ni][2 * half + 0] + bb.x,
                                       acc[mi][ni][2 * half + 1] + bb.y);
                if (RELU_OUT) { o.x = fmaxf(o.x, 0.f); o.y = fmaxf(o.y, 0.f); }
                if (MSG_OUT) {
                    const int   sr = half ? s1 : s0;
                    const float cr = half ? c1 : c0;
                    const float2 hv = *reinterpret_cast<const float2*>(hfeat + (size_t)sr * N + gn);
                    o.x = cr * o.x * hv.x; o.y = cr * o.y * hv.y;
                }
                if (SCATTER_OUT) {
                    const int dr = half ? d1 : d0;
                    asm volatile("red.global.add.v2.f32 [%0], {%1, %2};"
                                 :: "l"(C + (size_t)dr * N + gn), "f"(o.x), "f"(o.y) : "memory");
                } else if (OUT_SPLIT) {
                    const uint32_t hp = pack_bf16x2(o.x, o.y);
                    const float hx = __uint_as_float(hp << 16);
                    const float hy = __uint_as_float(hp & 0xFFFF0000u);
                    const uint32_t lp = pack_bf16x2(o.x - hx, o.y - hy);
                    *reinterpret_cast<uint32_t*>(Ch + (size_t)gmr * N + gn) = hp;
                    *reinterpret_cast<uint32_t*>(Cl + (size_t)gmr * N + gn) = lp;
                } else {
                    *reinterpret_cast<float2*>(C + (size_t)gmr * N + gn) = o;
                }
            }
        }
    }
}

// ---------------------------------------------------------------------------
// per-edge cosine: cos[e] = dot(h[s],h[d]) * inv[s] * inv[d]   (warp/edge)
// ---------------------------------------------------------------------------
template<int F>
__global__ void cos_kernel(const float* __restrict__ h,
                           const float* __restrict__ invn,
                           const int* __restrict__ src,
                           const int* __restrict__ dst,
                           float* __restrict__ cosv)
{
    const int e    = blockIdx.x * 8 + (threadIdx.x >> 5);
    const int lane = threadIdx.x & 31;
    const int s = src[e];
    const int d = dst[e];
    const float4* hs4 = reinterpret_cast<const float4*>(h + (size_t)s * F);
    const float4* hd4 = reinterpret_cast<const float4*>(h + (size_t)d * F);
    float dot = 0.f;
    #pragma unroll
    for (int j = 0; j < F / 128; j++) {
        const float4 a = hs4[lane + j * 32];
        const float4 b = hd4[lane + j * 32];
        dot += a.x * b.x + a.y * b.y + a.z * b.z + a.w * b.w;
    }
    #pragma unroll
    for (int o = 16; o > 0; o >>= 1) dot += __shfl_xor_sync(0xFFFFFFFFu, dot, o);
    if (lane == 0) cosv[e] = dot * invn[s] * invn[d];
}

// ---------------------------------------------------------------------------
// w1+msg1 fused, emitting pre-split bf16:
//   m1 = cos*w1*nf[src]  -> m1h/m1l ;  relu(w1) -> rwh/rwl
// ---------------------------------------------------------------------------
__global__ void w1msg_kernel(const float* __restrict__ ef, const float* __restrict__ We,
                             const float* __restrict__ be,
                             const int* __restrict__ src,
                             const float* __restrict__ cosv,
                             const float* __restrict__ nf,
                             __nv_bfloat16* __restrict__ m1h, __nv_bfloat16* __restrict__ m1l,
                             __nv_bfloat16* __restrict__ rwh, __nv_bfloat16* __restrict__ rwl)
{
    const int idx = blockIdx.x * 256 + threadIdx.x;
    const int e = idx >> 7;
    const int j = idx & 127;
    const float e0 = ef[2 * e];
    const float e1 = ef[2 * e + 1];
    const float w = fmaf(e1, We[128 + j], fmaf(e0, We[j], be[j]));
    const float m = cosv[e] * w * nf[(size_t)src[e] * 128 + j];
    const float rw = fmaxf(w, 0.f);
    const __nv_bfloat16 mh = __float2bfloat16(m);
    m1h[idx] = mh;
    m1l[idx] = __float2bfloat16(m - __bfloat162float(mh));
    const __nv_bfloat16 rh = __float2bfloat16(rw);
    rwh[idx] = rh;
    rwl[idx] = __float2bfloat16(rw - __bfloat162float(rh));
}

// ---------------------------------------------------------------------------
// per-node inverse norm
// ---------------------------------------------------------------------------
template<int F>
__global__ void norm_kernel(const float* __restrict__ h, float* __restrict__ invn,
                            int n_nodes)
{
    const int n = blockIdx.x * 8 + (threadIdx.x >> 5);
    if (n >= n_nodes) return;
    const int lane = threadIdx.x & 31;
    const float4* h4 = reinterpret_cast<const float4*>(h + (size_t)n * F);
    float ss = 0.f;
    #pragma unroll
    for (int j = 0; j < F / 128; j++) {
        float4 v = h4[lane + j * 32];
        ss += v.x * v.x + v.y * v.y + v.z * v.z + v.w * v.w;
    }
    #pragma unroll
    for (int o = 16; o > 0; o >>= 1) ss += __shfl_xor_sync(0xFFFFFFFFu, ss, o);
    if (lane == 0) invn[n] = 1.f / fmaxf(sqrtf(ss), 1e-12f);
}

// ---------------------------------------------------------------------------
// degree
// ---------------------------------------------------------------------------
__global__ void deg_kernel(const int* __restrict__ dst, int* __restrict__ deg)
{
    const int e = blockIdx.x * 256 + threadIdx.x;
    if (e < NE) atomicAdd(&deg[dst[e]], 1);
}

// ---------------------------------------------------------------------------
// cat[n, 0:F] = h; cat[n, F:2F] = hN / max(deg, 1)
// ---------------------------------------------------------------------------
template<int F>
__global__ void cat_kernel(const float* __restrict__ h,
                           const float* __restrict__ hN,
                           const int* __restrict__ deg,
                           float* __restrict__ out, int n_nodes)
{
    const int idx = blockIdx.x * 256 + threadIdx.x;
    if (idx >= n_nodes * 2 * F) return;
    const int n = idx / (2 * F);
    const int k = idx - n * 2 * F;
    float v;
    if (k < F) v = h[(size_t)n * F + k];
    else       v = hN[(size_t)n * F + (k - F)] / fmaxf((float)deg[n], 1.f);
    out[idx] = v;
}

// ---------------------------------------------------------------------------
// launch
// ---------------------------------------------------------------------------
extern "C" void kernel_launch(void* const* d_in, const int* in_sizes, int n_in,
                              void* d_out, int out_size)
{
    (void)in_sizes; (void)n_in; (void)out_size;

    const float* nf   = (const float*)d_in[0];
    const float* ef   = (const float*)d_in[1];
    const int*   src  = (const int*)  d_in[2];
    const int*   dst  = (const int*)  d_in[3];
    const float* We1  = (const float*)d_in[4];
    const float* be1  = (const float*)d_in[5];
    const float* Wr1a = (const float*)d_in[6];
    const float* br1a = (const float*)d_in[7];
    const float* Wr1b = (const float*)d_in[8];
    const float* br1b = (const float*)d_in[9];
    const float* Wl1  = (const float*)d_in[10];
    const float* bl1  = (const float*)d_in[11];
    const float* We2  = (const float*)d_in[12];
    const float* be2  = (const float*)d_in[13];
    const float* Wr2a = (const float*)d_in[14];
    const float* br2a = (const float*)d_in[15];
    const float* Wr2b = (const float*)d_in[16];
    const float* br2b = (const float*)d_in[17];
    const float* Wl2  = (const float*)d_in[18];
    const float* bl2  = (const float*)d_in[19];
    float* out = (float*)d_out;

    float *p_h1, *p_hN, *p_cat, *p_inv, *p_cos;
    int*   p_deg;
    __nv_bfloat16 *p_bwh, *p_bwl, *p_p1h, *p_p1l, *p_p2h, *p_p2l, *p_rwh, *p_rwl;
    cudaGetSymbolAddress((void**)&p_h1,  g_h1);
    cudaGetSymbolAddress((void**)&p_hN,  g_hN);
    cudaGetSymbolAddress((void**)&p_cat, g_cat);
    cudaGetSymbolAddress((void**)&p_inv, g_inv);
    cudaGetSymbolAddress((void**)&p_cos, g_cos);
    cudaGetSymbolAddress((void**)&p_deg, g_deg);
    cudaGetSymbolAddress((void**)&p_bwh, g_bwh);
    cudaGetSymbolAddress((void**)&p_bwl, g_bwl);
    cudaGetSymbolAddress((void**)&p_p1h, g_p1h);
    cudaGetSymbolAddress((void**)&p_p1l, g_p1l);
    cudaGetSymbolAddress((void**)&p_p2h, g_p2h);
    cudaGetSymbolAddress((void**)&p_p2l, g_p2l);
    cudaGetSymbolAddress((void**)&p_rwh, g_rwh);
    cudaGetSymbolAddress((void**)&p_rwl, g_rwl);

    // instantiations + dynamic SMEM
    //  edge GEMMs (A bf16, double-buffered): 4*18432 + 2*CTA_N*144
    //  node GEMMs (A fp32, stage+convert) : 2*18432 + 2*CTA_N*144 + 32768
    constexpr int SM_BF128 = 4 * 18432 + 2 * 128 * 144;           // 110592
    constexpr int SM_FP128 = 2 * 18432 + 2 * 128 * 144 + 32768;   // 106496
    constexpr int SM_FP32N = 2 * 18432 + 2 * 32  * 144 + 32768;   // 78848

    auto Gsplit = gemm_mma<128, true,  true,  false, false, true >;  // r = relu(A@B+b) -> split
    auto Gscat  = gemm_mma<128, true,  true,  false, true,  false>;  // hN[dst] += relu(A@B+b)
    auto Gmsg   = gemm_mma<128, true,  false, true,  false, true >;  // m2 = cos*(A@B+b)*h1[src] -> split
    auto Gnode  = gemm_mma<128, false, true,  false, false, false>;  // node GEMM fp32
    auto Gcls   = gemm_mma<32,  false, false, false, false, false>;  // classifier
    cudaFuncSetAttribute(Gsplit, cudaFuncAttributeMaxDynamicSharedMemorySize, SM_BF128);
    cudaFuncSetAttribute(Gscat,  cudaFuncAttributeMaxDynamicSharedMemorySize, SM_BF128);
    cudaFuncSetAttribute(Gmsg,   cudaFuncAttributeMaxDynamicSharedMemorySize, SM_BF128);
    cudaFuncSetAttribute(Gnode,  cudaFuncAttributeMaxDynamicSharedMemorySize, SM_FP128);
    cudaFuncSetAttribute(Gcls,   cudaFuncAttributeMaxDynamicSharedMemorySize, SM_FP32N);

    const int EG = NE / 128;              // 6250 edge M-tiles
    const int VG = (NN + 127) / 128;      // 391 node M-tiles

    // ---- zero accumulators first ----
    cudaMemsetAsync(p_deg, 0, NN * sizeof(int));
    cudaMemsetAsync(p_hN, 0, (size_t)NN * F1 * sizeof(float));

    // ---- prep ----
    conv_w_kernel<<<(128 * 128 + 255) / 256, 256>>>(Wr1a, 128, 128, p_bwh + 0,     p_bwl + 0);
    conv_w_kernel<<<(128 * 128 + 255) / 256, 256>>>(Wr1b, 128, 128, p_bwh + 16384, p_bwl + 16384);
    norm_kernel<F1><<<(NN + 7) / 8, 256>>>(nf, p_inv, NN);
    cos_kernel<F1><<<NE / 8, 256>>>(nf, p_inv, src, dst, p_cos);
    w1msg_kernel<<<(NE * F1) / 256, 256>>>(ef, We1, be1, src, p_cos, nf,
                                           p_p1h, p_p1l, p_rwh, p_rwl);
    deg_kernel<<<(NE + 255) / 256, 256>>>(dst, p_deg);

    // ======================= layer 1 =======================
    // Ge1a: r1 = relu(m1 @ Wr1a + br1a) -> split into p2
    Gsplit<<<dim3(EG, 1), 256, SM_BF128>>>(
        nullptr, p_p1h, p_p1l, p_bwh + 0, p_bwl + 0, br1a,
        nullptr, p_p2h, p_p2l, NE, 128, 128, nullptr, nullptr, nullptr, nullptr);

    // G1b: hN[dst] += relu(r1 @ Wr1b + br1b)
    Gscat<<<dim3(EG, 1), 256, SM_BF128>>>(
        nullptr, p_p2h, p_p2l, p_bwh + 16384, p_bwl + 16384, br1b,
        p_hN, nullptr, nullptr, NE, 128, 128, nullptr, nullptr, nullptr, dst);

    // remaining weight pre-splits (independent)
    conv_w_kernel<<<(128 * 256 + 255) / 256, 256>>>(We2,  128, 256, p_bwh + 32768,  p_bwl + 32768);
    conv_w_kernel<<<(256 * 256 + 255) / 256, 256>>>(Wr2a, 256, 256, p_bwh + 65536,  p_bwl + 65536);
    conv_w_kernel<<<(256 * 256 + 255) / 256, 256>>>(Wr2b, 256, 256, p_bwh + 131072, p_bwl + 131072);
    conv_w_kernel<<<(256 * 256 + 255) / 256, 256>>>(Wl1,  256, 256, p_bwh + 196608, p_bwl + 196608);
    conv_w_kernel<<<(512 * 32  + 255) / 256, 256>>>(Wl2,  512, 32,  p_bwh + 262144, p_bwl + 262144);

    cat_kernel<F1><<<(NN * 2 * F1 + 255) / 256, 256>>>(nf, p_hN, p_deg, p_cat, NN);

    // Gl1: h1 = relu(cat @ Wl1 + bl1)
    Gnode<<<dim3(VG, 2), 256, SM_FP128>>>(
        p_cat, nullptr, nullptr, p_bwh + 196608, p_bwl + 196608, bl1,
        p_h1, nullptr, nullptr, NN, 256, 256, nullptr, nullptr, nullptr, nullptr);

    // ======================= layer 2 =======================
    norm_kernel<HF><<<(NN + 7) / 8, 256>>>(p_h1, p_inv, NN);
    cos_kernel<HF><<<NE / 8, 256>>>(p_h1, p_inv, src, dst, p_cos);
    cudaMemsetAsync(p_hN, 0, (size_t)NN * HF * sizeof(float));

    // Ge2: m2 = cos * (relu(w1) @ We2 + be2) * h1[src] -> split into p1
    Gmsg<<<dim3(EG, 2), 256, SM_BF128>>>(
        nullptr, p_rwh, p_rwl, p_bwh + 32768, p_bwl + 32768, be2,
        nullptr, p_p1h, p_p1l, NE, 128, 256, p_cos, p_h1, src, nullptr);

    // G2a: r2 = relu(m2 @ Wr2a + br2a) -> split into p2
    Gsplit<<<dim3(EG, 2), 256, SM_BF128>>>(
        nullptr, p_p1h, p_p1l, p_bwh + 65536, p_bwl + 65536, br2a,
        nullptr, p_p2h, p_p2l, NE, 256, 256, nullptr, nullptr, nullptr, nullptr);

    // G2b: hN[dst] += relu(r2 @ Wr2b + br2b)
    Gscat<<<dim3(EG, 2), 256, SM_BF128>>>(
        nullptr, p_p2h, p_p2l, p_bwh + 131072, p_bwl + 131072, br2b,
        p_hN, nullptr, nullptr, NE, 256, 256, nullptr, nullptr, nullptr, dst);

    cat_kernel<HF><<<(NN * 2 * HF + 255) / 256, 256>>>(p_h1, p_hN, p_deg, p_cat, NN);

    // Gl2: out = cat @ Wl2 + bl2
    Gcls<<<dim3(VG, 1), 256, SM_FP32N>>>(
        p_cat, nullptr, nullptr, p_bwh + 262144, p_bwl + 262144, bl2,
        out, nullptr, nullptr, NN, 512, 32, nullptr, nullptr, nullptr, nullptr);
}

// round 16
// speedup vs baseline: 1.2910x; 1.0409x over previous
#include <cuda_runtime.h>
#include <cuda_bf16.h>
#include <math.h>
#include <stdint.h>

// ---------------------------------------------------------------------------
// Problem constants
// ---------------------------------------------------------------------------
static constexpr int NN = 50000;    // nodes
static constexpr int NE = 800000;   // edges
static constexpr int F1 = 128;      // in_feats
static constexpr int HF = 256;      // h_feats
static constexpr int CF = 32;       // classes

// ---------------------------------------------------------------------------
// Scratch (device globals -- no allocation allowed)
// ---------------------------------------------------------------------------
__device__ __align__(16) __nv_bfloat16 g_p1h[(size_t)NE * HF];
__device__ __align__(16) __nv_bfloat16 g_p1l[(size_t)NE * HF];
__device__ __align__(16) __nv_bfloat16 g_p2h[(size_t)NE * HF];
__device__ __align__(16) __nv_bfloat16 g_p2l[(size_t)NE * HF];
__device__ __align__(16) __nv_bfloat16 g_rwh[(size_t)NE * F1];
__device__ __align__(16) __nv_bfloat16 g_rwl[(size_t)NE * F1];

__device__ __align__(16) float g_h1 [(size_t)NN * HF];
__device__ __align__(16) float g_hN [(size_t)NN * HF];
__device__ float g_inv[NN];
__device__ float g_cos[NE];
__device__ int   g_deg[NN];

// split-bf16 weights, pre-transposed to [N, K] K-major
static constexpr size_t WT_TOTAL = 278528;
__device__ __align__(16) __nv_bfloat16 g_bwh[WT_TOTAL];
__device__ __align__(16) __nv_bfloat16 g_bwl[WT_TOTAL];

// ---------------------------------------------------------------------------
// helpers
// ---------------------------------------------------------------------------
__device__ __forceinline__ uint32_t smem_u32(const void* p) {
    uint32_t a;
    asm("{ .reg .u64 t; cvta.to.shared.u64 t, %1; cvt.u32.u64 %0, t; }" : "=r"(a) : "l"(p));
    return a;
}

__device__ __forceinline__ void ldm4(uint32_t& r0, uint32_t& r1, uint32_t& r2, uint32_t& r3,
                                     uint32_t addr) {
    asm volatile("ldmatrix.sync.aligned.m8n8.x4.shared.b16 {%0,%1,%2,%3}, [%4];"
                 : "=r"(r0), "=r"(r1), "=r"(r2), "=r"(r3) : "r"(addr));
}

__device__ __forceinline__ void mma16816(float* c, const uint32_t* a, const uint32_t* b) {
    asm volatile("mma.sync.aligned.m16n8k16.row.col.f32.bf16.bf16.f32 "
                 "{%0,%1,%2,%3}, {%4,%5,%6,%7}, {%8,%9}, {%0,%1,%2,%3};"
                 : "+f"(c[0]), "+f"(c[1]), "+f"(c[2]), "+f"(c[3])
                 : "r"(a[0]), "r"(a[1]), "r"(a[2]), "r"(a[3]), "r"(b[0]), "r"(b[1]));
}

// split one fp32 pair into packed bf16 hi + bf16 lo
__device__ __forceinline__ uint32_t split2(float a, float b, uint32_t& lo) {
    __nv_bfloat16 ha = __float2bfloat16(a), hb = __float2bfloat16(b);
    float ra = a - __bfloat162float(ha);
    float rb = b - __bfloat162float(hb);
    __nv_bfloat16 la = __float2bfloat16(ra), lb = __float2bfloat16(rb);
    lo = (uint32_t)__bfloat16_as_ushort(la) | ((uint32_t)__bfloat16_as_ushort(lb) << 16);
    return (uint32_t)__bfloat16_as_ushort(ha) | ((uint32_t)__bfloat16_as_ushort(hb) << 16);
}

// pack float2 -> bf16x2 (x low, y high)
__device__ __forceinline__ uint32_t pack_bf16x2(float x, float y) {
    uint32_t r;
    asm("cvt.rn.bf16x2.f32 %0, %1, %2;" : "=r"(r) : "f"(y), "f"(x));
    return r;
}

static constexpr int RS = 144;           // SMEM row stride bytes (64 bf16 + pad)
static constexpr int AT = 128 * RS;      // one A part (hi or lo): 18432

// ---------------------------------------------------------------------------
// Weight pre-transform: W[K,N] fp32 -> Bt_hi/Bt_lo [N,K] bf16
// ---------------------------------------------------------------------------
__global__ void conv_w_kernel(const float* __restrict__ W, int K, int N,
                              __nv_bfloat16* __restrict__ hi, __nv_bfloat16* __restrict__ lo)
{
    const int idx = blockIdx.x * 256 + threadIdx.x;
    if (idx >= K * N) return;
    const int k = idx / N;
    const int n = idx - k * N;
    const float x = W[idx];
    const __nv_bfloat16 h = __float2bfloat16(x);
    const float r = x - __bfloat162float(h);
    hi[(size_t)n * K + k] = h;
    lo[(size_t)n * K + k] = __float2bfloat16(r);
}

// ---------------------------------------------------------------------------
// bf16 split-3 GEMM (A pre-split bf16 hi/lo, cp.async double-buffered).
// Epilogue: bias (+relu) (+msg) then scatter / split-store / fp32 store.
// ---------------------------------------------------------------------------
template<int CTA_N, bool RELU_OUT, bool MSG_OUT, bool SCATTER_OUT, bool OUT_SPLIT>
__launch_bounds__(256, 2)
__global__ void gemm_mma(const __nv_bfloat16* __restrict__ Ah,
                         const __nv_bfloat16* __restrict__ Al,
                         const __nv_bfloat16* __restrict__ Bh,
                         const __nv_bfloat16* __restrict__ Bl,
                         const float* __restrict__ bias,
                         float* __restrict__ C,
                         __nv_bfloat16* __restrict__ Ch,
                         __nv_bfloat16* __restrict__ Cl,
                         int M, int K, int N,
                         const float* __restrict__ cosv,
                         const float* __restrict__ hfeat,
                         const int* __restrict__ src,
                         const int* __restrict__ dst)
{
    extern __shared__ char sm[];
    constexpr int S_B  = 4 * AT;
    constexpr int SPAN = CTA_N / 2;
    constexpr int NI   = SPAN / 8;

    const int tid    = threadIdx.x;
    const int lane   = tid & 31;
    const int warp   = tid >> 5;
    const int warp_m = warp & 3;
    const int warp_n = warp >> 2;
    const int m0     = blockIdx.x * 128;
    const int n0     = blockIdx.y * CTA_N;

    const uint32_t sb = smem_u32(sm);
    const uint32_t lmo = ((lane & 7) + ((lane >> 3) & 1) * 8) * RS + (lane >> 4) * 16;
    const uint32_t b_base = sb + S_B + (uint32_t)(warp_n * SPAN) * RS + lmo;
    const uint32_t a_off  = (uint32_t)(warp_m * 32) * RS + lmo;

    float acc[2][NI][4];
    #pragma unroll
    for (int mi = 0; mi < 2; mi++)
        #pragma unroll
        for (int ni = 0; ni < NI; ni++)
            #pragma unroll
            for (int c = 0; c < 4; c++) acc[mi][ni][c] = 0.f;

    auto load_b = [&](int kc) {
        #pragma unroll
        for (int i = 0; i < CTA_N / 32; i++) {
            const int slot = tid + i * 256;
            const int n    = slot >> 3;
            const int grp  = slot & 7;
            const size_t go = (size_t)(n0 + n) * K + kc * 64 + grp * 8;
            const uint4 vh = *reinterpret_cast<const uint4*>(Bh + go);
            const uint4 vl = *reinterpret_cast<const uint4*>(Bl + go);
            const int off = n * RS + grp * 16;
            *reinterpret_cast<uint4*>(sm + S_B + off) = vh;
            *reinterpret_cast<uint4*>(sm + S_B + CTA_N * RS + off) = vl;
        }
    };

    auto do_mma = [&](uint32_t abase) {
        #pragma unroll
        for (int s = 0; s < 3; s++) {
            const uint32_t ab = abase + ((s == 2) ? (uint32_t)AT : 0u);
            const uint32_t bb = b_base + ((s == 1) ? (uint32_t)(CTA_N * RS) : 0u);
            #pragma unroll
            for (int ks = 0; ks < 4; ks++) {
                uint32_t a[2][4];
                ldm4(a[0][0], a[0][1], a[0][2], a[0][3], ab + ks * 32);
                ldm4(a[1][0], a[1][1], a[1][2], a[1][3], ab + 16 * RS + ks * 32);
                uint32_t b[NI][2];
                #pragma unroll
                for (int p = 0; p < NI / 2; p++) {
                    uint32_t r0, r1, r2, r3;
                    ldm4(r0, r1, r2, r3, bb + (uint32_t)(p * 16) * RS + ks * 32);
                    b[2 * p][0] = r0; b[2 * p + 1][0] = r1;
                    b[2 * p][1] = r2; b[2 * p + 1][1] = r3;
                }
                #pragma unroll
                for (int mi = 0; mi < 2; mi++)
                    #pragma unroll
                    for (int ni = 0; ni < NI; ni++)
                        mma16816(acc[mi][ni], a[mi], b[ni]);
            }
        }
    };

    auto cp_a = [&](int kc, int buf) {
        #pragma unroll
        for (int i = 0; i < 4; i++) {
            const int slot = tid + i * 256;
            const int row  = slot >> 3;
            const int grp  = slot & 7;
            const int gm   = m0 + row;
            const bool ok  = (gm < M);
            const size_t go = (size_t)(ok ? gm : m0) * K + kc * 64 + grp * 8;
            const uint32_t dh = sb + (uint32_t)(buf * 2 * AT) + (uint32_t)(row * RS + grp * 16);
            const int ssz = ok ? 16 : 0;
            asm volatile("cp.async.cg.shared.global [%0], [%1], 16, %2;"
                         :: "r"(dh), "l"(Ah + go), "r"(ssz) : "memory");
            asm volatile("cp.async.cg.shared.global [%0], [%1], 16, %2;"
                         :: "r"(dh + AT), "l"(Al + go), "r"(ssz) : "memory");
        }
        asm volatile("cp.async.commit_group;" ::: "memory");
    };

    const int NC = K >> 6;
    int buf = 0;
    cp_a(0, 0);
    for (int kc = 0; kc < NC; kc++) {
        if (kc + 1 < NC) cp_a(kc + 1, buf ^ 1);
        load_b(kc);
        if (kc + 1 < NC) asm volatile("cp.async.wait_group 1;" ::: "memory");
        else             asm volatile("cp.async.wait_group 0;" ::: "memory");
        __syncthreads();
        do_mma(sb + (uint32_t)(buf * 2 * AT) + a_off);
        __syncthreads();
        buf ^= 1;
    }

    // ---- epilogue ----
    const int g = lane >> 2;
    const int t = lane & 3;
    #pragma unroll
    for (int mi = 0; mi < 2; mi++) {
        const int gm = m0 + warp_m * 32 + mi * 16 + g;
        int s0 = 0, s1 = 0, d0 = 0, d1 = 0;
        float c0 = 0.f, c1 = 0.f;
        if (MSG_OUT) {
            if (gm < M)     { s0 = src[gm];     c0 = cosv[gm]; }
            if (gm + 8 < M) { s1 = src[gm + 8]; c1 = cosv[gm + 8]; }
        }
        if (SCATTER_OUT) {
            if (gm < M)     d0 = dst[gm];
            if (gm + 8 < M) d1 = dst[gm + 8];
        }
        #pragma unroll
        for (int ni = 0; ni < NI; ni++) {
            const int gn = n0 + warp_n * SPAN + ni * 8 + t * 2;
            const float2 bb = *reinterpret_cast<const float2*>(bias + gn);
            #pragma unroll
            for (int half = 0; half < 2; half++) {
                const int gmr = gm + half * 8;
                if (gmr >= M) continue;
                float2 o = make_float2(acc[mi][ni][2 * half + 0] + bb.x,
                                       acc[mi][ni][2 * half + 1] + bb.y);
                if (RELU_OUT) { o.x = fmaxf(o.x, 0.f); o.y = fmaxf(o.y, 0.f); }
                if (MSG_OUT) {
                    const int   sr = half ? s1 : s0;
                    const float cr = half ? c1 : c0;
                    const float2 hv = *reinterpret_cast<const float2*>(hfeat + (size_t)sr * N + gn);
                    o.x = cr * o.x * hv.x; o.y = cr * o.y * hv.y;
                }
                if (SCATTER_OUT) {
                    const int dr = half ? d1 : d0;
                    asm volatile("red.global.add.v2.f32 [%0], {%1, %2};"
                                 :: "l"(C + (size_t)dr * N + gn), "f"(o.x), "f"(o.y) : "memory");
                } else if (OUT_SPLIT) {
                    const uint32_t hp = pack_bf16x2(o.x, o.y);
                    const float hx = __uint_as_float(hp << 16);
                    const float hy = __uint_as_float(hp & 0xFFFF0000u);
                    const uint32_t lp = pack_bf16x2(o.x - hx, o.y - hy);
                    *reinterpret_cast<uint32_t*>(Ch + (size_t)gmr * N + gn) = hp;
                    *reinterpret_cast<uint32_t*>(Cl + (size_t)gmr * N + gn) = lp;
                } else {
                    *reinterpret_cast<float2*>(C + (size_t)gmr * N + gn) = o;
                }
            }
        }
    }
}

// ---------------------------------------------------------------------------
// Chained layer-1 kernel: hN[dst] += relu( relu(m1@B1+b1) @ B2 + b2 )
// K=N=128.  GEMM1's epilogue writes split r1 into the SMEM A buffers
// (buf = warp_n; each N-half is one 64-col K-chunk of GEMM2), then GEMM2
// runs over SMEM-resident A and scatters.
// ---------------------------------------------------------------------------
__launch_bounds__(256, 2)
__global__ void gemm_chain(const __nv_bfloat16* __restrict__ Ah,
                           const __nv_bfloat16* __restrict__ Al,
                           const __nv_bfloat16* __restrict__ B1h,
                           const __nv_bfloat16* __restrict__ B1l,
                           const float* __restrict__ b1,
                           const __nv_bfloat16* __restrict__ B2h,
                           const __nv_bfloat16* __restrict__ B2l,
                           const float* __restrict__ b2,
                           float* __restrict__ hN,
                           const int* __restrict__ dst,
                           int M)
{
    extern __shared__ char sm[];
    constexpr int K = 128, N = 128;
    constexpr int S_B = 4 * AT;
    constexpr int NI  = 8;

    const int tid    = threadIdx.x;
    const int lane   = tid & 31;
    const int warp   = tid >> 5;
    const int warp_m = warp & 3;
    const int warp_n = warp >> 2;
    const int m0     = blockIdx.x * 128;

    const uint32_t sb = smem_u32(sm);
    const uint32_t lmo = ((lane & 7) + ((lane >> 3) & 1) * 8) * RS + (lane >> 4) * 16;
    const uint32_t b_base = sb + S_B + (uint32_t)(warp_n * 64) * RS + lmo;
    const uint32_t a_off  = (uint32_t)(warp_m * 32) * RS + lmo;

    float acc[2][NI][4];
    auto zero_acc = [&]() {
        #pragma unroll
        for (int mi = 0; mi < 2; mi++)
            #pragma unroll
            for (int ni = 0; ni < NI; ni++)
                #pragma unroll
                for (int c = 0; c < 4; c++) acc[mi][ni][c] = 0.f;
    };
    zero_acc();

    auto load_b = [&](const __nv_bfloat16* Bh, const __nv_bfloat16* Bl, int kc) {
        #pragma unroll
        for (int i = 0; i < 4; i++) {
            const int slot = tid + i * 256;
            const int n    = slot >> 3;
            const int grp  = slot & 7;
            const size_t go = (size_t)n * K + kc * 64 + grp * 8;
            const uint4 vh = *reinterpret_cast<const uint4*>(Bh + go);
            const uint4 vl = *reinterpret_cast<const uint4*>(Bl + go);
            const int off = n * RS + grp * 16;
            *reinterpret_cast<uint4*>(sm + S_B + off) = vh;
            *reinterpret_cast<uint4*>(sm + S_B + 128 * RS + off) = vl;
        }
    };

    auto do_mma = [&](uint32_t abase) {
        #pragma unroll
        for (int s = 0; s < 3; s++) {
            const uint32_t ab = abase + ((s == 2) ? (uint32_t)AT : 0u);
            const uint32_t bb = b_base + ((s == 1) ? (uint32_t)(128 * RS) : 0u);
            #pragma unroll
            for (int ks = 0; ks < 4; ks++) {
                uint32_t a[2][4];
                ldm4(a[0][0], a[0][1], a[0][2], a[0][3], ab + ks * 32);
                ldm4(a[1][0], a[1][1], a[1][2], a[1][3], ab + 16 * RS + ks * 32);
                uint32_t b[NI][2];
                #pragma unroll
                for (int p = 0; p < NI / 2; p++) {
                    uint32_t r0, r1, r2, r3;
                    ldm4(r0, r1, r2, r3, bb + (uint32_t)(p * 16) * RS + ks * 32);
                    b[2 * p][0] = r0; b[2 * p + 1][0] = r1;
                    b[2 * p][1] = r2; b[2 * p + 1][1] = r3;
                }
                #pragma unroll
                for (int mi = 0; mi < 2; mi++)
                    #pragma unroll
                    for (int ni = 0; ni < NI; ni++)
                        mma16816(acc[mi][ni], a[mi], b[ni]);
            }
        }
    };

    auto cp_a = [&](int kc, int buf) {
        #pragma unroll
        for (int i = 0; i < 4; i++) {
            const int slot = tid + i * 256;
            const int row  = slot >> 3;
            const int grp  = slot & 7;
            const int gm   = m0 + row;
            const bool ok  = (gm < M);
            const size_t go = (size_t)(ok ? gm : m0) * K + kc * 64 + grp * 8;
            const uint32_t dh = sb + (uint32_t)(buf * 2 * AT) + (uint32_t)(row * RS + grp * 16);
            const int ssz = ok ? 16 : 0;
            asm volatile("cp.async.cg.shared.global [%0], [%1], 16, %2;"
                         :: "r"(dh), "l"(Ah + go), "r"(ssz) : "memory");
            asm volatile("cp.async.cg.shared.global [%0], [%1], 16, %2;"
                         :: "r"(dh + AT), "l"(Al + go), "r"(ssz) : "memory");
        }
        asm volatile("cp.async.commit_group;" ::: "memory");
    };

    // ================= GEMM1: r1 = relu(m1 @ B1 + b1) =================
    cp_a(0, 0);
    cp_a(1, 1);
    for (int kc = 0; kc < 2; kc++) {
        load_b(B1h, B1l, kc);
        if (kc == 0) asm volatile("cp.async.wait_group 1;" ::: "memory");
        else         asm volatile("cp.async.wait_group 0;" ::: "memory");
        __syncthreads();
        do_mma(sb + (uint32_t)(kc * 2 * AT) + a_off);
        __syncthreads();
    }

    // ---- mid-epilogue: split r1 into SMEM A buffers (buf = warp_n) ----
    const int g = lane >> 2;
    const int t = lane & 3;
    {
        char* abuf = sm + warp_n * 2 * AT;
        #pragma unroll
        for (int mi = 0; mi < 2; mi++) {
            #pragma unroll
            for (int ni = 0; ni < NI; ni++) {
                const int col = ni * 8 + t * 2;            // local col in 0..63
                const float2 bb = *reinterpret_cast<const float2*>(b1 + warp_n * 64 + col);
                #pragma unroll
                for (int half = 0; half < 2; half++) {
                    const int row = warp_m * 32 + mi * 16 + g + half * 8;
                    float ox = fmaxf(acc[mi][ni][2 * half + 0] + bb.x, 0.f);
                    float oy = fmaxf(acc[mi][ni][2 * half + 1] + bb.y, 0.f);
                    const uint32_t hp = pack_bf16x2(ox, oy);
                    const float hx = __uint_as_float(hp << 16);
                    const float hy = __uint_as_float(hp & 0xFFFF0000u);
                    const uint32_t lp = pack_bf16x2(ox - hx, oy - hy);
                    const int off = row * RS + col * 2;
                    *reinterpret_cast<uint32_t*>(abuf + off) = hp;
                    *reinterpret_cast<uint32_t*>(abuf + AT + off) = lp;
                }
            }
        }
    }
    zero_acc();
    __syncthreads();

    // ================= GEMM2: relu(r1 @ B2 + b2) -> scatter =================
    for (int kc = 0; kc < 2; kc++) {
        load_b(B2h, B2l, kc);
        __syncthreads();
        do_mma(sb + (uint32_t)(kc * 2 * AT) + a_off);
        __syncthreads();
    }

    #pragma unroll
    for (int mi = 0; mi < 2; mi++) {
        const int gm = m0 + warp_m * 32 + mi * 16 + g;
        int d0 = 0, d1 = 0;
        if (gm < M)     d0 = dst[gm];
        if (gm + 8 < M) d1 = dst[gm + 8];
        #pragma unroll
        for (int ni = 0; ni < NI; ni++) {
            const int gn = warp_n * 64 + ni * 8 + t * 2;
            const float2 bb = *reinterpret_cast<const float2*>(b2 + gn);
            #pragma unroll
            for (int half = 0; half < 2; half++) {
                const int gmr = gm + half * 8;
                if (gmr >= M) continue;
                float2 o = make_float2(fmaxf(acc[mi][ni][2 * half + 0] + bb.x, 0.f),
                                       fmaxf(acc[mi][ni][2 * half + 1] + bb.y, 0.f));
                const int dr = half ? d1 : d0;
                asm volatile("red.global.add.v2.f32 [%0], {%1, %2};"
                             :: "l"(hN + (size_t)dr * N + gn), "f"(o.x), "f"(o.y) : "memory");
            }
        }
    }
}

// ---------------------------------------------------------------------------
// Node GEMM with fused concat A: chunk kc reads h (kc*64 < K1) or hN/deg.
// C = act( [h | hN/deg] @ B + bias ).  Direct LDG convert phase (small grids).
// ---------------------------------------------------------------------------
template<int CTA_N, bool RELU_OUT>
__launch_bounds__(256, 2)
__global__ void gemm_cat(const float* __restrict__ A1, int K1,
                         const float* __restrict__ A2,
                         const int* __restrict__ deg,
                         const __nv_bfloat16* __restrict__ Bh,
                         const __nv_bfloat16* __restrict__ Bl,
                         const float* __restrict__ bias,
                         float* __restrict__ C,
                         int M, int K, int N)
{
    extern __shared__ char sm[];
    constexpr int S_B  = 2 * AT;
    constexpr int SPAN = CTA_N / 2;
    constexpr int NI   = SPAN / 8;

    const int tid    = threadIdx.x;
    const int lane   = tid & 31;
    const int warp   = tid >> 5;
    const int warp_m = warp & 3;
    const int warp_n = warp >> 2;
    const int m0     = blockIdx.x * 128;
    const int n0     = blockIdx.y * CTA_N;
    const int K2     = K - K1;

    const uint32_t sb = smem_u32(sm);
    const uint32_t lmo = ((lane & 7) + ((lane >> 3) & 1) * 8) * RS + (lane >> 4) * 16;
    const uint32_t b_base = sb + S_B + (uint32_t)(warp_n * SPAN) * RS + lmo;
    const uint32_t a_base = sb + (uint32_t)(warp_m * 32) * RS + lmo;

    float acc[2][NI][4];
    #pragma unroll
    for (int mi = 0; mi < 2; mi++)
        #pragma unroll
        for (int ni = 0; ni < NI; ni++)
            #pragma unroll
            for (int c = 0; c < 4; c++) acc[mi][ni][c] = 0.f;

    const int NC = K >> 6;
    for (int kc = 0; kc < NC; kc++) {
        // ---- A chunk: load from h or hN/deg, split into SMEM ----
        const bool second = (kc * 64 >= K1);
        #pragma unroll
        for (int i = 0; i < 8; i++) {
            const int slot = tid + i * 256;
            const int row  = slot >> 4;
            const int c4   = slot & 15;
            const int gm   = m0 + row;
            float4 v = make_float4(0.f, 0.f, 0.f, 0.f);
            if (gm < M) {
                if (!second) {
                    v = *reinterpret_cast<const float4*>(A1 + (size_t)gm * K1 + kc * 64 + c4 * 4);
                } else {
                    v = *reinterpret_cast<const float4*>(A2 + (size_t)gm * K2 + (kc * 64 - K1) + c4 * 4);
                    const float dv = fmaxf((float)deg[gm], 1.f);
                    v.x /= dv; v.y /= dv; v.z /= dv; v.w /= dv;
                }
            }
            uint32_t l0, l1;
            const uint32_t h0 = split2(v.x, v.y, l0);
            const uint32_t h1 = split2(v.z, v.w, l1);
            const int off = row * RS + c4 * 8;
            *reinterpret_cast<uint2*>(sm + off) = make_uint2(h0, h1);
            *reinterpret_cast<uint2*>(sm + AT + off) = make_uint2(l0, l1);
        }
        // ---- B chunk ----
        #pragma unroll
        for (int i = 0; i < CTA_N / 32; i++) {
            const int slot = tid + i * 256;
            const int n    = slot >> 3;
            const int grp  = slot & 7;
            const size_t go = (size_t)(n0 + n) * K + kc * 64 + grp * 8;
            const uint4 vh = *reinterpret_cast<const uint4*>(Bh + go);
            const uint4 vl = *reinterpret_cast<const uint4*>(Bl + go);
            const int off = n * RS + grp * 16;
            *reinterpret_cast<uint4*>(sm + S_B + off) = vh;
            *reinterpret_cast<uint4*>(sm + S_B + CTA_N * RS + off) = vl;
        }
        __syncthreads();

        #pragma unroll
        for (int s = 0; s < 3; s++) {
            const uint32_t ab = a_base + ((s == 2) ? (uint32_t)AT : 0u);
            const uint32_t bb = b_base + ((s == 1) ? (uint32_t)(CTA_N * RS) : 0u);
            #pragma unroll
            for (int ks = 0; ks < 4; ks++) {
                uint32_t a[2][4];
                ldm4(a[0][0], a[0][1], a[0][2], a[0][3], ab + ks * 32);
                ldm4(a[1][0], a[1][1], a[1][2], a[1][3], ab + 16 * RS + ks * 32);
                uint32_t b[NI][2];
                #pragma unroll
                for (int p = 0; p < NI / 2; p++) {
                    uint32_t r0, r1, r2, r3;
                    ldm4(r0, r1, r2, r3, bb + (uint32_t)(p * 16) * RS + ks * 32);
                    b[2 * p][0] = r0; b[2 * p + 1][0] = r1;
                    b[2 * p][1] = r2; b[2 * p + 1][1] = r3;
                }
                #pragma unroll
                for (int mi = 0; mi < 2; mi++)
                    #pragma unroll
                    for (int ni = 0; ni < NI; ni++)
                        mma16816(acc[mi][ni], a[mi], b[ni]);
            }
        }
        __syncthreads();
    }

    const int g = lane >> 2;
    const int t = lane & 3;
    #pragma unroll
    for (int mi = 0; mi < 2; mi++) {
        const int gm = m0 + warp_m * 32 + mi * 16 + g;
        #pragma unroll
        for (int ni = 0; ni < NI; ni++) {
            const int gn = n0 + warp_n * SPAN + ni * 8 + t * 2;
            const float2 bb = *reinterpret_cast<const float2*>(bias + gn);
            #pragma unroll
            for (int half = 0; half < 2; half++) {
                const int gmr = gm + half * 8;
                if (gmr >= M) continue;
                float2 o = make_float2(acc[mi][ni][2 * half + 0] + bb.x,
                                       acc[mi][ni][2 * half + 1] + bb.y);
                if (RELU_OUT) { o.x = fmaxf(o.x, 0.f); o.y = fmaxf(o.y, 0.f); }
                *reinterpret_cast<float2*>(C + (size_t)gmr * N + gn) = o;
            }
        }
    }
}

// ---------------------------------------------------------------------------
// per-edge cosine: 4 edges per warp (8 lanes each)
// ---------------------------------------------------------------------------
template<int F>
__global__ void cos_kernel(const float* __restrict__ h,
                           const float* __restrict__ invn,
                           const int* __restrict__ src,
                           const int* __restrict__ dst,
                           float* __restrict__ cosv)
{
    const int e  = blockIdx.x * 32 + (threadIdx.x >> 3);
    const int l8 = threadIdx.x & 7;
    const int s = src[e];
    const int d = dst[e];
    const float4* hs4 = reinterpret_cast<const float4*>(h + (size_t)s * F);
    const float4* hd4 = reinterpret_cast<const float4*>(h + (size_t)d * F);
    float dot = 0.f;
    #pragma unroll
    for (int p = 0; p < F / 32; p++) {
        const float4 a = hs4[l8 + p * 8];
        const float4 b = hd4[l8 + p * 8];
        dot += a.x * b.x + a.y * b.y + a.z * b.z + a.w * b.w;
    }
    dot += __shfl_xor_sync(0xFFFFFFFFu, dot, 4);
    dot += __shfl_xor_sync(0xFFFFFFFFu, dot, 2);
    dot += __shfl_xor_sync(0xFFFFFFFFu, dot, 1);
    if (l8 == 0) cosv[e] = dot * invn[s] * invn[d];
}

// ---------------------------------------------------------------------------
// w1+msg1 fused, emitting pre-split bf16
// ---------------------------------------------------------------------------
__global__ void w1msg_kernel(const float* __restrict__ ef, const float* __restrict__ We,
                             const float* __restrict__ be,
                             const int* __restrict__ src,
                             const float* __restrict__ cosv,
                             const float* __restrict__ nf,
                             __nv_bfloat16* __restrict__ m1h, __nv_bfloat16* __restrict__ m1l,
                             __nv_bfloat16* __restrict__ rwh, __nv_bfloat16* __restrict__ rwl)
{
    const int idx = blockIdx.x * 256 + threadIdx.x;
    const int e = idx >> 7;
    const int j = idx & 127;
    const float e0 = ef[2 * e];
    const float e1 = ef[2 * e + 1];
    const float w = fmaf(e1, We[128 + j], fmaf(e0, We[j], be[j]));
    const float m = cosv[e] * w * nf[(size_t)src[e] * 128 + j];
    const float rw = fmaxf(w, 0.f);
    const __nv_bfloat16 mh = __float2bfloat16(m);
    m1h[idx] = mh;
    m1l[idx] = __float2bfloat16(m - __bfloat162float(mh));
    const __nv_bfloat16 rh = __float2bfloat16(rw);
    rwh[idx] = rh;
    rwl[idx] = __float2bfloat16(rw - __bfloat162float(rh));
}

// ---------------------------------------------------------------------------
// per-node inverse norm
// ---------------------------------------------------------------------------
template<int F>
__global__ void norm_kernel(const float* __restrict__ h, float* __restrict__ invn,
                            int n_nodes)
{
    const int n = blockIdx.x * 8 + (threadIdx.x >> 5);
    if (n >= n_nodes) return;
    const int lane = threadIdx.x & 31;
    const float4* h4 = reinterpret_cast<const float4*>(h + (size_t)n * F);
    float ss = 0.f;
    #pragma unroll
    for (int j = 0; j < F / 128; j++) {
        float4 v = h4[lane + j * 32];
        ss += v.x * v.x + v.y * v.y + v.z * v.z + v.w * v.w;
    }
    #pragma unroll
    for (int o = 16; o > 0; o >>= 1) ss += __shfl_xor_sync(0xFFFFFFFFu, ss, o);
    if (lane == 0) invn[n] = 1.f / fmaxf(sqrtf(ss), 1e-12f);
}

// ---------------------------------------------------------------------------
// degree
// ---------------------------------------------------------------------------
__global__ void deg_kernel(const int* __restrict__ dst, int* __restrict__ deg)
{
    const int e = blockIdx.x * 256 + threadIdx.x;
    if (e < NE) atomicAdd(&deg[dst[e]], 1);
}

// ---------------------------------------------------------------------------
// launch
// ---------------------------------------------------------------------------
extern "C" void kernel_launch(void* const* d_in, const int* in_sizes, int n_in,
                              void* d_out, int out_size)
{
    (void)in_sizes; (void)n_in; (void)out_size;

    const float* nf   = (const float*)d_in[0];
    const float* ef   = (const float*)d_in[1];
    const int*   src  = (const int*)  d_in[2];
    const int*   dst  = (const int*)  d_in[3];
    const float* We1  = (const float*)d_in[4];
    const float* be1  = (const float*)d_in[5];
    const float* Wr1a = (const float*)d_in[6];
    const float* br1a = (const float*)d_in[7];
    const float* Wr1b = (const float*)d_in[8];
    const float* br1b = (const float*)d_in[9];
    const float* Wl1  = (const float*)d_in[10];
    const float* bl1  = (const float*)d_in[11];
    const float* We2  = (const float*)d_in[12];
    const float* be2  = (const float*)d_in[13];
    const float* Wr2a = (const float*)d_in[14];
    const float* br2a = (const float*)d_in[15];
    const float* Wr2b = (const float*)d_in[16];
    const float* br2b = (const float*)d_in[17];
    const float* Wl2  = (const float*)d_in[18];
    const float* bl2  = (const float*)d_in[19];
    float* out = (float*)d_out;

    float *p_h1, *p_hN, *p_inv, *p_cos;
    int*   p_deg;
    __nv_bfloat16 *p_bwh, *p_bwl, *p_p1h, *p_p1l, *p_p2h, *p_p2l, *p_rwh, *p_rwl;
    cudaGetSymbolAddress((void**)&p_h1,  g_h1);
    cudaGetSymbolAddress((void**)&p_hN,  g_hN);
    cudaGetSymbolAddress((void**)&p_inv, g_inv);
    cudaGetSymbolAddress((void**)&p_cos, g_cos);
    cudaGetSymbolAddress((void**)&p_deg, g_deg);
    cudaGetSymbolAddress((void**)&p_bwh, g_bwh);
    cudaGetSymbolAddress((void**)&p_bwl, g_bwl);
    cudaGetSymbolAddress((void**)&p_p1h, g_p1h);
    cudaGetSymbolAddress((void**)&p_p1l, g_p1l);
    cudaGetSymbolAddress((void**)&p_p2h, g_p2h);
    cudaGetSymbolAddress((void**)&p_p2l, g_p2l);
    cudaGetSymbolAddress((void**)&p_rwh, g_rwh);
    cudaGetSymbolAddress((void**)&p_rwl, g_rwl);

    constexpr int SM_BF128 = 4 * 18432 + 2 * 128 * 144;   // 110592
    constexpr int SM_CT128 = 2 * 18432 + 2 * 128 * 144;   // 73728
    constexpr int SM_CT32  = 2 * 18432 + 2 * 32  * 144;   // 46080

    auto Gsplit = gemm_mma<128, true,  false, false, true >;
    auto Gscat  = gemm_mma<128, true,  false, true,  false>;
    auto Gmsg   = gemm_mma<128, false, true,  false, true >;
    auto Gcat1  = gemm_cat<128, true >;
    auto Gcat2  = gemm_cat<32,  false>;
    cudaFuncSetAttribute(Gsplit, cudaFuncAttributeMaxDynamicSharedMemorySize, SM_BF128);
    cudaFuncSetAttribute(Gscat,  cudaFuncAttributeMaxDynamicSharedMemorySize, SM_BF128);
    cudaFuncSetAttribute(Gmsg,   cudaFuncAttributeMaxDynamicSharedMemorySize, SM_BF128);
    cudaFuncSetAttribute(gemm_chain, cudaFuncAttributeMaxDynamicSharedMemorySize, SM_BF128);
    cudaFuncSetAttribute(Gcat1,  cudaFuncAttributeMaxDynamicSharedMemorySize, SM_CT128);
    cudaFuncSetAttribute(Gcat2,  cudaFuncAttributeMaxDynamicSharedMemorySize, SM_CT32);

    const int EG = NE / 128;              // 6250 edge M-tiles
    const int VG = (NN + 127) / 128;      // 391 node M-tiles

    // ---- zero accumulators first ----
    cudaMemsetAsync(p_deg, 0, NN * sizeof(int));
    cudaMemsetAsync(p_hN, 0, (size_t)NN * F1 * sizeof(float));

    // ---- prep ----
    conv_w_kernel<<<(128 * 128 + 255) / 256, 256>>>(Wr1a, 128, 128, p_bwh + 0,     p_bwl + 0);
    conv_w_kernel<<<(128 * 128 + 255) / 256, 256>>>(Wr1b, 128, 128, p_bwh + 16384, p_bwl + 16384);
    norm_kernel<F1><<<(NN + 7) / 8, 256>>>(nf, p_inv, NN);
    cos_kernel<F1><<<NE / 32, 256>>>(nf, p_inv, src, dst, p_cos);
    w1msg_kernel<<<(NE * F1) / 256, 256>>>(ef, We1, be1, src, p_cos, nf,
                                           p_p1h, p_p1l, p_rwh, p_rwl);
    deg_kernel<<<(NE + 255) / 256, 256>>>(dst, p_deg);

    // ======================= layer 1 =======================
    // chained: hN[dst] += relu( relu(m1@Wr1a+br1a) @ Wr1b + br1b )
    gemm_chain<<<EG, 256, SM_BF128>>>(
        p_p1h, p_p1l, p_bwh + 0, p_bwl + 0, br1a,
        p_bwh + 16384, p_bwl + 16384, br1b, p_hN, dst, NE);

    // remaining weight pre-splits (independent)
    conv_w_kernel<<<(128 * 256 + 255) / 256, 256>>>(We2,  128, 256, p_bwh + 32768,  p_bwl + 32768);
    conv_w_kernel<<<(256 * 256 + 255) / 256, 256>>>(Wr2a, 256, 256, p_bwh + 65536,  p_bwl + 65536);
    conv_w_kernel<<<(256 * 256 + 255) / 256, 256>>>(Wr2b, 256, 256, p_bwh + 131072, p_bwl + 131072);
    conv_w_kernel<<<(256 * 256 + 255) / 256, 256>>>(Wl1,  256, 256, p_bwh + 196608, p_bwl + 196608);
    conv_w_kernel<<<(512 * 32  + 255) / 256, 256>>>(Wl2,  512, 32,  p_bwh + 262144, p_bwl + 262144);

    // Gl1 (fused concat): h1 = relu([nf | hN/deg] @ Wl1 + bl1)
    Gcat1<<<dim3(VG, 2), 256, SM_CT128>>>(
        nf, 128, p_hN, p_deg, p_bwh + 196608, p_bwl + 196608, bl1,
        p_h1, NN, 256, 256);

    // ======================= layer 2 =======================
    norm_kernel<HF><<<(NN + 7) / 8, 256>>>(p_h1, p_inv, NN);
    cos_kernel<HF><<<NE / 32, 256>>>(p_h1, p_inv, src, dst, p_cos);
    cudaMemsetAsync(p_hN, 0, (size_t)NN * HF * sizeof(float));

    // Ge2: m2 = cos * (relu(w1) @ We2 + be2) * h1[src] -> split into p2
    Gmsg<<<dim3(EG, 2), 256, SM_BF128>>>(
        p_rwh, p_rwl, p_bwh + 32768, p_bwl + 32768, be2,
        nullptr, p_p2h, p_p2l, NE, 128, 256, p_cos, p_h1, src, nullptr);

    // G2a: r2 = relu(m2 @ Wr2a + br2a) -> split into p1
    Gsplit<<<dim3(EG, 2), 256, SM_BF128>>>(
        p_p2h, p_p2l, p_bwh + 65536, p_bwl + 65536, br2a,
        nullptr, p_p1h, p_p1l, NE, 256, 256, nullptr, nullptr, nullptr, nullptr);

    // G2b: hN[dst] += relu(r2 @ Wr2b + br2b)
    Gscat<<<dim3(EG, 2), 256, SM_BF128>>>(
        p_p1h, p_p1l, p_bwh + 131072, p_bwl + 131072, br2b,
        p_hN, nullptr, nullptr, NE, 256, 256, nullptr, nullptr, nullptr, dst);

    // Gl2 (fused concat): out = [h1 | hN/deg] @ Wl2 + bl2
    Gcat2<<<dim3(VG, 1), 256, SM_CT32>>>(
        p_h1, 256, p_hN, p_deg, p_bwh + 262144, p_bwl + 262144, bl2,
        out, NN, 512, 32);
}